// round 9
// baseline (speedup 1.0000x reference)
#include <cuda_runtime.h>
#include <cuda_bf16.h>
#include <math.h>
#include <stdint.h>

// Problem constants
#define N_   1024
#define B_   4
#define C_   1024
#define H_   16
#define HD_  64
#define M_   (N_*B_)
#define LOGIT_MAX 4.6051701859880914f  // log(100)

// Scratch (allocation-free rule: __device__ globals)
__device__ float g_q[M_*C_];
__device__ float g_k[M_*C_];
__device__ float g_v[M_*C_];
__device__ float g_x[M_*C_];

// ===========================================================================
// bf16x3 split-precision tensor-core GEMM (mma.sync + ldmatrix):
//   C[m][n] = sum_k A[m][k] * W[n][k] + bias[n]
// A: (M x K) fp32 row-major, W: (N x K) fp32 row-major.
// Each fp32 x = x_hi(bf16) + x_lo(bf16 of residual); accumulate
//   Ah*Bh + Ah*Bl + Al*Bh  in fp32  (error ~1e-5, near-fp32).
// Block tile 128x128, BK=32 fp32-k per iter, 256 threads (8 warps 2x4),
// warp tile 64x32. mma.sync.m16n8k16.bf16, fragments via ldmatrix.x4.
// Smem rows: 32 bf16 = 64B, chunk-XOR swizzle -> conflict-free STS & LDSM.
// ===========================================================================
#define GBM 128
#define GBN 128
#define GBK 32
#define SLABB (128*64)          // one 128-row x 32-bf16 slab = 8 KB
#define BUFB  (4*SLABB)         // Ah, Al, Bh, Bl
#define GSMEM (2*BUFB)          // 64 KB double-buffered

__device__ __forceinline__ uint32_t smem_u32(const void* p) {
    uint32_t a;
    asm("{ .reg .u64 t; cvta.to.shared.u64 t, %1; cvt.u32.u64 %0, t; }"
        : "=r"(a) : "l"(p));
    return a;
}

__device__ __forceinline__ void ldsm_x4(uint32_t* r, uint32_t addr) {
    asm volatile("ldmatrix.sync.aligned.m8n8.x4.shared.b16 {%0,%1,%2,%3}, [%4];"
                 : "=r"(r[0]), "=r"(r[1]), "=r"(r[2]), "=r"(r[3]) : "r"(addr));
}

__device__ __forceinline__ void mma_bf16(float* c, const uint32_t* a, const uint32_t* b) {
    asm volatile(
        "mma.sync.aligned.m16n8k16.row.col.f32.bf16.bf16.f32 "
        "{%0,%1,%2,%3}, {%4,%5,%6,%7}, {%8,%9}, {%0,%1,%2,%3};"
        : "+f"(c[0]), "+f"(c[1]), "+f"(c[2]), "+f"(c[3])
        : "r"(a[0]), "r"(a[1]), "r"(a[2]), "r"(a[3]), "r"(b[0]), "r"(b[1]));
}

// Load one 16-float strip (row, k-half) for A and B
__device__ __forceinline__ void ldg_strip(
    const float* __restrict__ A, const float* __restrict__ W,
    int m0, int n0, int K, int k0, int row, int half,
    float4* ra, float4* rb)
{
    const float4* ga = (const float4*)&A[(size_t)(m0 + row) * K + k0 + half * 16];
    const float4* gw = (const float4*)&W[(size_t)(n0 + row) * K + k0 + half * 16];
    #pragma unroll
    for (int i = 0; i < 4; i++) { ra[i] = ga[i]; rb[i] = gw[i]; }
}

// Convert 16 floats -> 16 bf16 hi + 16 bf16 lo, store as two 16B chunks each.
__device__ __forceinline__ void cvt_sts_strip(
    const float4* r, uint32_t hi_base, uint32_t lo_base, int row, int half)
{
    const float* f = (const float*)r;
    uint32_t h[8], l[8];
    #pragma unroll
    for (int i = 0; i < 8; i++) {
        __nv_bfloat16 h0 = __float2bfloat16_rn(f[2*i]);
        __nv_bfloat16 h1 = __float2bfloat16_rn(f[2*i+1]);
        float l0 = f[2*i]   - __bfloat162float(h0);
        float l1 = f[2*i+1] - __bfloat162float(h1);
        __nv_bfloat162 hp; hp.x = h0; hp.y = h1;
        __nv_bfloat162 lp = __floats2bfloat162_rn(l0, l1);
        h[i] = *(uint32_t*)&hp;
        l[i] = *(uint32_t*)&lp;
    }
    const uint32_t xr = (uint32_t)((row >> 1) & 3);
    const uint32_t rb = (uint32_t)row * 64;
    uint32_t c0 = (uint32_t)(half * 2);
    uint32_t a0 = rb + ((c0)     ^ xr) * 16;
    uint32_t a1 = rb + ((c0 + 1) ^ xr) * 16;
    asm volatile("st.shared.v4.b32 [%0], {%1,%2,%3,%4};" ::
        "r"(hi_base + a0), "r"(h[0]), "r"(h[1]), "r"(h[2]), "r"(h[3]));
    asm volatile("st.shared.v4.b32 [%0], {%1,%2,%3,%4};" ::
        "r"(hi_base + a1), "r"(h[4]), "r"(h[5]), "r"(h[6]), "r"(h[7]));
    asm volatile("st.shared.v4.b32 [%0], {%1,%2,%3,%4};" ::
        "r"(lo_base + a0), "r"(l[0]), "r"(l[1]), "r"(l[2]), "r"(l[3]));
    asm volatile("st.shared.v4.b32 [%0], {%1,%2,%3,%4};" ::
        "r"(lo_base + a1), "r"(l[4]), "r"(l[5]), "r"(l[6]), "r"(l[7]));
}

__global__ __launch_bounds__(256) void gemm_bf16x3_kernel(
    const float* __restrict__ A, const float* __restrict__ W,
    const float* __restrict__ bias, float* __restrict__ C,
    int M, int N, int K)
{
    extern __shared__ char smem[];
    const uint32_t sbase = smem_u32(smem);
    const int tid  = threadIdx.x;
    const int warp = tid >> 5, lane = tid & 31;
    const int wm = warp >> 2, wn = warp & 3;     // 2 x 4 warp grid
    const int m0 = blockIdx.y * GBM, n0 = blockIdx.x * GBN;

    // producer strip: row = tid/2, k-half = tid&1
    const int prow = tid >> 1, phalf = tid & 1;

    // ldmatrix lane address components
    // A (x4 covers m16 x k16): row = base + (lane&15), ksel = lane>>4
    const int a_lrow = lane & 15;
    const uint32_t a_ksel = (uint32_t)(lane >> 4);
    // B (x4 covers n16 x k16): row = base + ((lane>>4)<<3) + (lane&7), bsel = (lane>>3)&1
    const int b_lrow = ((lane >> 4) << 3) + (lane & 7);
    const uint32_t b_ksel = (uint32_t)((lane >> 3) & 1);

    uint32_t a_off[4], a_xor[4];    // per mt
    #pragma unroll
    for (int mt = 0; mt < 4; mt++) {
        int r = wm * 64 + mt * 16 + a_lrow;
        a_off[mt] = (uint32_t)r * 64;
        a_xor[mt] = (uint32_t)((r >> 1) & 3);
    }
    uint32_t b_off[2], b_xor[2];    // per nt-pair
    #pragma unroll
    for (int np = 0; np < 2; np++) {
        int r = wn * 32 + np * 16 + b_lrow;
        b_off[np] = (uint32_t)r * 64;
        b_xor[np] = (uint32_t)((r >> 1) & 3);
    }

    float acc[4][4][4];
    #pragma unroll
    for (int i = 0; i < 4; i++)
        #pragma unroll
        for (int j = 0; j < 4; j++)
            #pragma unroll
            for (int r = 0; r < 4; r++) acc[i][j][r] = 0.f;

    float4 ra[4], rb[4];

    // Prologue: tile 0 -> buffer 0
    ldg_strip(A, W, m0, n0, K, 0, prow, phalf, ra, rb);
    cvt_sts_strip(ra, sbase,             sbase + SLABB,     prow, phalf);
    cvt_sts_strip(rb, sbase + 2*SLABB,   sbase + 3*SLABB,   prow, phalf);
    __syncthreads();

    const int NT = K / GBK;   // 32
    for (int t = 0; t < NT; t++) {
        const int buf = t & 1;
        if (t + 1 < NT)
            ldg_strip(A, W, m0, n0, K, (t + 1) * GBK, prow, phalf, ra, rb);

        const uint32_t Ah = sbase + buf * BUFB;
        const uint32_t Al = Ah + SLABB;
        const uint32_t Bh = Ah + 2 * SLABB;
        const uint32_t Bl = Ah + 3 * SLABB;

        #pragma unroll
        for (int ks = 0; ks < 2; ks++) {
            uint32_t ah[4][4], al[4][4], bh[2][4], bl[2][4];
            #pragma unroll
            for (int mt = 0; mt < 4; mt++) {
                uint32_t c = (((uint32_t)(ks << 1) + a_ksel) ^ a_xor[mt]) * 16;
                ldsm_x4(ah[mt], Ah + a_off[mt] + c);
                ldsm_x4(al[mt], Al + a_off[mt] + c);
            }
            #pragma unroll
            for (int np = 0; np < 2; np++) {
                uint32_t c = (((uint32_t)(ks << 1) + b_ksel) ^ b_xor[np]) * 16;
                ldsm_x4(bh[np], Bh + b_off[np] + c);
                ldsm_x4(bl[np], Bl + b_off[np] + c);
            }
            #pragma unroll
            for (int mt = 0; mt < 4; mt++)
                #pragma unroll
                for (int nt = 0; nt < 4; nt++) {
                    const uint32_t* bhf = &bh[nt >> 1][(nt & 1) * 2];
                    const uint32_t* blf = &bl[nt >> 1][(nt & 1) * 2];
                    mma_bf16(acc[mt][nt], ah[mt], bhf);
                    mma_bf16(acc[mt][nt], ah[mt], blf);
                    mma_bf16(acc[mt][nt], al[mt], bhf);
                }
        }

        if (t + 1 < NT) {
            const uint32_t nb = sbase + (buf ^ 1) * BUFB;
            cvt_sts_strip(ra, nb,             nb + SLABB,     prow, phalf);
            cvt_sts_strip(rb, nb + 2*SLABB,   nb + 3*SLABB,   prow, phalf);
        }
        __syncthreads();
    }

    // Epilogue: bias add, float2 stores
    const int lr = lane >> 2, lc = lane & 3;
    #pragma unroll
    for (int mt = 0; mt < 4; mt++) {
        const int row = m0 + wm * 64 + mt * 16 + lr;
        #pragma unroll
        for (int nt = 0; nt < 4; nt++) {
            const int col = n0 + wn * 32 + nt * 8 + 2 * lc;
            const float bx = bias[col], by = bias[col + 1];
            float2 o0 = { acc[mt][nt][0] + bx, acc[mt][nt][1] + by };
            float2 o1 = { acc[mt][nt][2] + bx, acc[mt][nt][3] + by };
            *(float2*)&C[(size_t)row * N + col]       = o0;
            *(float2*)&C[(size_t)(row + 8) * N + col] = o1;
        }
    }
}

// ---------------------------------------------------------------------------
// Per-(row, head) L2 normalize; optionally fold exp(min(ls, LOGIT_MAX)) scale
// ---------------------------------------------------------------------------
__global__ __launch_bounds__(256) void norm_kernel(
    float* __restrict__ buf, const float* __restrict__ ls, int applyScale)
{
    int gw = (blockIdx.x * 256 + threadIdx.x) >> 5;
    int lane = threadIdx.x & 31;
    if (gw >= M_ * H_) return;
    int m = gw >> 4;
    int h = gw & 15;
    float* p = buf + (size_t)m * C_ + h * HD_;
    float v0 = p[lane], v1 = p[lane + 32];
    float ss = v0 * v0 + v1 * v1;
    #pragma unroll
    for (int o = 16; o; o >>= 1) ss += __shfl_xor_sync(0xffffffffu, ss, o);
    float inv = rsqrtf(fmaxf(ss, 1e-24f));
    if (applyScale) inv *= __expf(fminf(ls[h], LOGIT_MAX));
    p[lane] = v0 * inv;
    p[lane + 32] = v1 * inv;
}

// ---------------------------------------------------------------------------
// Flash attention, fp32. Grid: (N/64, B*H). Block: 256 threads.
// ---------------------------------------------------------------------------
#define QS 68
#define KS 72
#define PS 65

__global__ __launch_bounds__(256) void attn_kernel(
    const float* __restrict__ q, const float* __restrict__ k,
    const float* __restrict__ v, float* __restrict__ x)
{
    extern __shared__ float sm[];
    float* Qs = sm;
    float* Ks = Qs + 64 * QS;
    float* Vs = Ks + 64 * KS;
    float* Ps = Vs + 64 * KS;

    const int tid = threadIdx.x;
    const int r = tid >> 2;
    const int g = tid & 3;
    const int qt = blockIdx.x;
    const int bh = blockIdx.y;
    const int b = bh >> 4, h = bh & 15;
    const int n0 = qt * 64;
    const size_t rs = (size_t)B_ * C_;
    const size_t hb = (size_t)b * C_ + h * HD_;

    const float* qbase = q + hb;
    const float* kbase = k + hb;
    const float* vbase = v + hb;

    for (int idx = tid; idx < 64 * 16; idx += 256) {
        int row = idx >> 4, d4 = idx & 15;
        *(float4*)&Qs[row * QS + d4 * 4] =
            *(const float4*)&qbase[(size_t)(n0 + row) * rs + d4 * 4];
    }

    float4 o0 = {0,0,0,0}, o1 = {0,0,0,0}, o2 = {0,0,0,0}, o3 = {0,0,0,0};
    float mrow = -1e30f, lrow = 0.f;

    for (int kt = 0; kt < 16; kt++) {
        __syncthreads();
        int kn0 = kt * 64;
        for (int idx = tid; idx < 64 * 16; idx += 256) {
            int row = idx >> 4, d4 = idx & 15;
            size_t go = (size_t)(kn0 + row) * rs + d4 * 4;
            *(float4*)&Ks[row * KS + d4 * 4] = *(const float4*)&kbase[go];
            *(float4*)&Vs[row * KS + d4 * 4] = *(const float4*)&vbase[go];
        }
        __syncthreads();

        float s[16];
        #pragma unroll
        for (int j = 0; j < 16; j++) s[j] = 0.f;
        #pragma unroll
        for (int d4 = 0; d4 < 16; d4++) {
            float4 q4 = *(float4*)&Qs[r * QS + d4 * 4];
            #pragma unroll
            for (int j = 0; j < 16; j++) {
                float4 k4 = *(float4*)&Ks[(g + 4 * j) * KS + d4 * 4];
                s[j] += q4.x * k4.x + q4.y * k4.y + q4.z * k4.z + q4.w * k4.w;
            }
        }

        float tmax = s[0];
        #pragma unroll
        for (int j = 1; j < 16; j++) tmax = fmaxf(tmax, s[j]);
        tmax = fmaxf(tmax, __shfl_xor_sync(0xffffffffu, tmax, 1));
        tmax = fmaxf(tmax, __shfl_xor_sync(0xffffffffu, tmax, 2));
        float mnew = fmaxf(mrow, tmax);
        float corr = __expf(mrow - mnew);
        lrow *= corr;
        o0.x *= corr; o0.y *= corr; o0.z *= corr; o0.w *= corr;
        o1.x *= corr; o1.y *= corr; o1.z *= corr; o1.w *= corr;
        o2.x *= corr; o2.y *= corr; o2.z *= corr; o2.w *= corr;
        o3.x *= corr; o3.y *= corr; o3.z *= corr; o3.w *= corr;

        float psum = 0.f;
        #pragma unroll
        for (int j = 0; j < 16; j++) {
            float pv = __expf(s[j] - mnew);
            psum += pv;
            Ps[r * PS + g + 4 * j] = pv;
        }
        psum += __shfl_xor_sync(0xffffffffu, psum, 1);
        psum += __shfl_xor_sync(0xffffffffu, psum, 2);
        lrow += psum;
        mrow = mnew;
        __syncwarp();

        #pragma unroll
        for (int j = 0; j < 64; j++) {
            float pv = Ps[r * PS + j];
            const float* vr = &Vs[j * KS + g * 4];
            float4 v0 = *(const float4*)&vr[0];
            float4 v1 = *(const float4*)&vr[16];
            float4 v2 = *(const float4*)&vr[32];
            float4 v3 = *(const float4*)&vr[48];
            o0.x += pv * v0.x; o0.y += pv * v0.y; o0.z += pv * v0.z; o0.w += pv * v0.w;
            o1.x += pv * v1.x; o1.y += pv * v1.y; o1.z += pv * v1.z; o1.w += pv * v1.w;
            o2.x += pv * v2.x; o2.y += pv * v2.y; o2.z += pv * v2.z; o2.w += pv * v2.w;
            o3.x += pv * v3.x; o3.y += pv * v3.y; o3.z += pv * v3.z; o3.w += pv * v3.w;
        }
        __syncwarp();
    }

    float invl = 1.f / lrow;
    float* xb = x + hb + (size_t)(n0 + r) * rs + g * 4;
    float4 w0 = {o0.x*invl, o0.y*invl, o0.z*invl, o0.w*invl};
    float4 w1 = {o1.x*invl, o1.y*invl, o1.z*invl, o1.w*invl};
    float4 w2 = {o2.x*invl, o2.y*invl, o2.z*invl, o2.w*invl};
    float4 w3 = {o3.x*invl, o3.y*invl, o3.z*invl, o3.w*invl};
    *(float4*)&xb[0]  = w0;
    *(float4*)&xb[16] = w1;
    *(float4*)&xb[32] = w2;
    *(float4*)&xb[48] = w3;
}

// ---------------------------------------------------------------------------
// Launcher
// ---------------------------------------------------------------------------
extern "C" void kernel_launch(void* const* d_in, const int* in_sizes, int n_in,
                              void* d_out, int out_size)
{
    const float* query = (const float*)d_in[0];
    const float* key   = (const float*)d_in[1];
    const float* value = (const float*)d_in[2];
    const float* ipw   = (const float*)d_in[3];   // (3C, C)
    const float* ipb   = (const float*)d_in[4];   // (3C)
    const float* ls    = (const float*)d_in[5];   // (H,1,1)
    const float* outw  = (const float*)d_in[6];   // (C, C)
    const float* outb  = (const float*)d_in[7];   // (C)
    float* out = (float*)d_out;

    float *q, *k, *v, *x;
    cudaGetSymbolAddress((void**)&q, g_q);
    cudaGetSymbolAddress((void**)&k, g_k);
    cudaGetSymbolAddress((void**)&v, g_v);
    cudaGetSymbolAddress((void**)&x, g_x);

    dim3 gg(C_ / GBN, M_ / GBM);   // (8, 32)
    static int gemm_attr_set = 0;
    if (!gemm_attr_set) {
        cudaFuncSetAttribute(gemm_bf16x3_kernel,
                             cudaFuncAttributeMaxDynamicSharedMemorySize, GSMEM);
        gemm_attr_set = 1;
    }

    // In-projections
    gemm_bf16x3_kernel<<<gg, 256, GSMEM>>>(query, ipw,                   ipb,         q, M_, C_, C_);
    gemm_bf16x3_kernel<<<gg, 256, GSMEM>>>(key,   ipw + (size_t)C_*C_,   ipb + C_,    k, M_, C_, C_);
    gemm_bf16x3_kernel<<<gg, 256, GSMEM>>>(value, ipw + (size_t)2*C_*C_, ipb + 2*C_,  v, M_, C_, C_);

    // L2-normalize heads; fold logit scale into q
    norm_kernel<<<(M_ * H_) / 8, 256>>>(q, ls, 1);
    norm_kernel<<<(M_ * H_) / 8, 256>>>(k, ls, 0);

    // Flash attention (fp32)
    const int smem = (64 * QS + 64 * KS + 64 * KS + 64 * PS) * (int)sizeof(float);
    static int attn_attr_set = 0;
    if (!attn_attr_set) {
        cudaFuncSetAttribute(attn_kernel,
                             cudaFuncAttributeMaxDynamicSharedMemorySize, smem);
        attn_attr_set = 1;
    }
    attn_kernel<<<dim3(N_ / 64, B_ * H_), 256, smem>>>(q, k, v, x);

    // Output projection
    gemm_bf16x3_kernel<<<gg, 256, GSMEM>>>(x, outw, outb, out, M_, C_, C_);
}

// round 10
// speedup vs baseline: 1.0367x; 1.0367x over previous
#include <cuda_runtime.h>
#include <cuda_bf16.h>
#include <math.h>
#include <stdint.h>

// Problem constants
#define N_   1024
#define B_   4
#define C_   1024
#define H_   16
#define HD_  64
#define M_   (N_*B_)
#define LOGIT_MAX 4.6051701859880914f  // log(100)

// Scratch (allocation-free rule: __device__ globals)
__device__ float g_q[M_*C_];
__device__ float g_k[M_*C_];
__device__ float g_v[M_*C_];
__device__ float g_x[M_*C_];
// Pre-split bf16 operands
__device__ __nv_bfloat16 g_ah[M_*C_];       // A-side hi (reused: query/key/value/x)
__device__ __nv_bfloat16 g_al[M_*C_];       // A-side lo
__device__ __nv_bfloat16 g_wh[4*C_*C_];     // weights hi: ipw (3M) + outw (1M)
__device__ __nv_bfloat16 g_wl[4*C_*C_];     // weights lo

// ===========================================================================
// Split kernel: fp32 -> bf16 hi + bf16 lo(residual). Memory-bound.
// ===========================================================================
__global__ __launch_bounds__(256) void split_bf16_kernel(
    const float* __restrict__ src, __nv_bfloat16* __restrict__ hi,
    __nv_bfloat16* __restrict__ lo, int n4)
{
    int i = blockIdx.x * 256 + threadIdx.x;
    if (i >= n4) return;
    float4 f = ((const float4*)src)[i];
    __nv_bfloat16 h0 = __float2bfloat16_rn(f.x);
    __nv_bfloat16 h1 = __float2bfloat16_rn(f.y);
    __nv_bfloat16 h2 = __float2bfloat16_rn(f.z);
    __nv_bfloat16 h3 = __float2bfloat16_rn(f.w);
    __nv_bfloat162 l01 = __floats2bfloat162_rn(f.x - __bfloat162float(h0),
                                               f.y - __bfloat162float(h1));
    __nv_bfloat162 l23 = __floats2bfloat162_rn(f.z - __bfloat162float(h2),
                                               f.w - __bfloat162float(h3));
    __nv_bfloat162 h01; h01.x = h0; h01.y = h1;
    __nv_bfloat162 h23; h23.x = h2; h23.y = h3;
    uint2 hv = { *(uint32_t*)&h01, *(uint32_t*)&h23 };
    uint2 lv = { *(uint32_t*)&l01, *(uint32_t*)&l23 };
    ((uint2*)hi)[i] = hv;
    ((uint2*)lo)[i] = lv;
}

// ===========================================================================
// bf16x3 split-precision tensor-core GEMM (pre-converted operands):
//   C[m][n] = sum_k A[m][k] * W[n][k] + bias[n]
// Operands already split into bf16 hi/lo (row-major M x K / N x K).
// Accumulate Ah*Bh + Ah*Bl + Al*Bh in fp32 (error ~1e-5).
// Block tile 128x128, BK=32, 256 threads (8 warps 2x4), warp tile 64x32.
// mma.sync.m16n8k16.bf16, fragments via ldmatrix.x4.
// Smem rows: 32 bf16 = 64B, chunk-XOR swizzle -> conflict-free STS & LDSM.
// ===========================================================================
#define GBM 128
#define GBN 128
#define GBK 32
#define SLABB (128*64)          // one 128-row x 32-bf16 slab = 8 KB
#define BUFB  (4*SLABB)         // Ah, Al, Bh, Bl
#define GSMEM (2*BUFB)          // 64 KB double-buffered

__device__ __forceinline__ uint32_t smem_u32(const void* p) {
    uint32_t a;
    asm("{ .reg .u64 t; cvta.to.shared.u64 t, %1; cvt.u32.u64 %0, t; }"
        : "=r"(a) : "l"(p));
    return a;
}

__device__ __forceinline__ void ldsm_x4(uint32_t* r, uint32_t addr) {
    asm volatile("ldmatrix.sync.aligned.m8n8.x4.shared.b16 {%0,%1,%2,%3}, [%4];"
                 : "=r"(r[0]), "=r"(r[1]), "=r"(r[2]), "=r"(r[3]) : "r"(addr));
}

__device__ __forceinline__ void mma_bf16(float* c, const uint32_t* a, const uint32_t* b) {
    asm volatile(
        "mma.sync.aligned.m16n8k16.row.col.f32.bf16.bf16.f32 "
        "{%0,%1,%2,%3}, {%4,%5,%6,%7}, {%8,%9}, {%0,%1,%2,%3};"
        : "+f"(c[0]), "+f"(c[1]), "+f"(c[2]), "+f"(c[3])
        : "r"(a[0]), "r"(a[1]), "r"(a[2]), "r"(a[3]), "r"(b[0]), "r"(b[1]));
}

__device__ __forceinline__ void sts16(uint32_t addr, uint4 v) {
    asm volatile("st.shared.v4.b32 [%0], {%1,%2,%3,%4};" ::
        "r"(addr), "r"(v.x), "r"(v.y), "r"(v.z), "r"(v.w));
}

__global__ __launch_bounds__(256) void gemm_bf16x3_kernel(
    const __nv_bfloat16* __restrict__ Ah_g, const __nv_bfloat16* __restrict__ Al_g,
    const __nv_bfloat16* __restrict__ Wh_g, const __nv_bfloat16* __restrict__ Wl_g,
    const float* __restrict__ bias, float* __restrict__ C,
    int M, int N, int K)
{
    extern __shared__ char smem[];
    const uint32_t sbase = smem_u32(smem);
    const int tid  = threadIdx.x;
    const int warp = tid >> 5, lane = tid & 31;
    const int wm = warp >> 2, wn = warp & 3;     // 2 x 4 warp grid
    const int m0 = blockIdx.y * GBM, n0 = blockIdx.x * GBN;

    // producer strip: row = tid/2, k-half = tid&1 (16 bf16 = 32 B per slab)
    const int prow = tid >> 1, phalf = tid & 1;
    const size_t aoff = (size_t)(m0 + prow) * K + phalf * 16;
    const size_t boff = (size_t)(n0 + prow) * K + phalf * 16;
    // swizzled STS byte offsets within a slab
    const uint32_t xr = (uint32_t)((prow >> 1) & 3);
    const uint32_t rbyte = (uint32_t)prow * 64;
    const uint32_t c0 = (uint32_t)(phalf * 2);
    const uint32_t sa0 = rbyte + ((c0)     ^ xr) * 16;
    const uint32_t sa1 = rbyte + ((c0 + 1) ^ xr) * 16;

    // ldmatrix lane address components (identical to verified R9 layout)
    const int a_lrow = lane & 15;
    const uint32_t a_ksel = (uint32_t)(lane >> 4);
    const int b_lrow = ((lane >> 4) << 3) + (lane & 7);
    const uint32_t b_ksel = (uint32_t)((lane >> 3) & 1);

    uint32_t a_off[4], a_xor[4];
    #pragma unroll
    for (int mt = 0; mt < 4; mt++) {
        int r = wm * 64 + mt * 16 + a_lrow;
        a_off[mt] = (uint32_t)r * 64;
        a_xor[mt] = (uint32_t)((r >> 1) & 3);
    }
    uint32_t b_off[2], b_xor[2];
    #pragma unroll
    for (int np = 0; np < 2; np++) {
        int r = wn * 32 + np * 16 + b_lrow;
        b_off[np] = (uint32_t)r * 64;
        b_xor[np] = (uint32_t)((r >> 1) & 3);
    }

    float acc[4][4][4];
    #pragma unroll
    for (int i = 0; i < 4; i++)
        #pragma unroll
        for (int j = 0; j < 4; j++)
            #pragma unroll
            for (int r = 0; r < 4; r++) acc[i][j][r] = 0.f;

    uint4 rAh0, rAh1, rAl0, rAl1, rBh0, rBh1, rBl0, rBl1;

    // Prologue: tile 0 -> regs -> buffer 0
    {
        const __nv_bfloat16* pa = Ah_g + aoff;
        const __nv_bfloat16* pl = Al_g + aoff;
        const __nv_bfloat16* pb = Wh_g + boff;
        const __nv_bfloat16* pw = Wl_g + boff;
        rAh0 = *(const uint4*)pa; rAh1 = *(const uint4*)(pa + 8);
        rAl0 = *(const uint4*)pl; rAl1 = *(const uint4*)(pl + 8);
        rBh0 = *(const uint4*)pb; rBh1 = *(const uint4*)(pb + 8);
        rBl0 = *(const uint4*)pw; rBl1 = *(const uint4*)(pw + 8);
    }
    {
        const uint32_t Ah = sbase, Al = sbase + SLABB;
        const uint32_t Bh = sbase + 2*SLABB, Bl = sbase + 3*SLABB;
        sts16(Ah + sa0, rAh0); sts16(Ah + sa1, rAh1);
        sts16(Al + sa0, rAl0); sts16(Al + sa1, rAl1);
        sts16(Bh + sa0, rBh0); sts16(Bh + sa1, rBh1);
        sts16(Bl + sa0, rBl0); sts16(Bl + sa1, rBl1);
    }
    __syncthreads();

    const int NT = K / GBK;   // 32
    for (int t = 0; t < NT; t++) {
        const int buf = t & 1;
        if (t + 1 < NT) {
            const size_t ko = (size_t)(t + 1) * GBK;
            const __nv_bfloat16* pa = Ah_g + aoff + ko;
            const __nv_bfloat16* pl = Al_g + aoff + ko;
            const __nv_bfloat16* pb = Wh_g + boff + ko;
            const __nv_bfloat16* pw = Wl_g + boff + ko;
            rAh0 = *(const uint4*)pa; rAh1 = *(const uint4*)(pa + 8);
            rAl0 = *(const uint4*)pl; rAl1 = *(const uint4*)(pl + 8);
            rBh0 = *(const uint4*)pb; rBh1 = *(const uint4*)(pb + 8);
            rBl0 = *(const uint4*)pw; rBl1 = *(const uint4*)(pw + 8);
        }

        const uint32_t Ah = sbase + buf * BUFB;
        const uint32_t Al = Ah + SLABB;
        const uint32_t Bh = Ah + 2 * SLABB;
        const uint32_t Bl = Ah + 3 * SLABB;

        #pragma unroll
        for (int ks = 0; ks < 2; ks++) {
            uint32_t ah[4][4], al[4][4], bh[2][4], bl[2][4];
            #pragma unroll
            for (int mt = 0; mt < 4; mt++) {
                uint32_t c = (((uint32_t)(ks << 1) + a_ksel) ^ a_xor[mt]) * 16;
                ldsm_x4(ah[mt], Ah + a_off[mt] + c);
                ldsm_x4(al[mt], Al + a_off[mt] + c);
            }
            #pragma unroll
            for (int np = 0; np < 2; np++) {
                uint32_t c = (((uint32_t)(ks << 1) + b_ksel) ^ b_xor[np]) * 16;
                ldsm_x4(bh[np], Bh + b_off[np] + c);
                ldsm_x4(bl[np], Bl + b_off[np] + c);
            }
            #pragma unroll
            for (int mt = 0; mt < 4; mt++)
                #pragma unroll
                for (int nt = 0; nt < 4; nt++) {
                    const uint32_t* bhf = &bh[nt >> 1][(nt & 1) * 2];
                    const uint32_t* blf = &bl[nt >> 1][(nt & 1) * 2];
                    mma_bf16(acc[mt][nt], ah[mt], bhf);
                    mma_bf16(acc[mt][nt], ah[mt], blf);
                    mma_bf16(acc[mt][nt], al[mt], bhf);
                }
        }

        if (t + 1 < NT) {
            const uint32_t nb = sbase + (buf ^ 1) * BUFB;
            sts16(nb + sa0, rAh0);             sts16(nb + sa1, rAh1);
            sts16(nb + SLABB + sa0, rAl0);     sts16(nb + SLABB + sa1, rAl1);
            sts16(nb + 2*SLABB + sa0, rBh0);   sts16(nb + 2*SLABB + sa1, rBh1);
            sts16(nb + 3*SLABB + sa0, rBl0);   sts16(nb + 3*SLABB + sa1, rBl1);
        }
        __syncthreads();
    }

    // Epilogue: bias add, float2 stores
    const int lr = lane >> 2, lc = lane & 3;
    #pragma unroll
    for (int mt = 0; mt < 4; mt++) {
        const int row = m0 + wm * 64 + mt * 16 + lr;
        #pragma unroll
        for (int nt = 0; nt < 4; nt++) {
            const int col = n0 + wn * 32 + nt * 8 + 2 * lc;
            const float bx = bias[col], by = bias[col + 1];
            float2 o0 = { acc[mt][nt][0] + bx, acc[mt][nt][1] + by };
            float2 o1 = { acc[mt][nt][2] + bx, acc[mt][nt][3] + by };
            *(float2*)&C[(size_t)row * N + col]       = o0;
            *(float2*)&C[(size_t)(row + 8) * N + col] = o1;
        }
    }
}

// ---------------------------------------------------------------------------
// Per-(row, head) L2 normalize; optionally fold exp(min(ls, LOGIT_MAX)) scale
// ---------------------------------------------------------------------------
__global__ __launch_bounds__(256) void norm_kernel(
    float* __restrict__ buf, const float* __restrict__ ls, int applyScale)
{
    int gw = (blockIdx.x * 256 + threadIdx.x) >> 5;
    int lane = threadIdx.x & 31;
    if (gw >= M_ * H_) return;
    int m = gw >> 4;
    int h = gw & 15;
    float* p = buf + (size_t)m * C_ + h * HD_;
    float v0 = p[lane], v1 = p[lane + 32];
    float ss = v0 * v0 + v1 * v1;
    #pragma unroll
    for (int o = 16; o; o >>= 1) ss += __shfl_xor_sync(0xffffffffu, ss, o);
    float inv = rsqrtf(fmaxf(ss, 1e-24f));
    if (applyScale) inv *= __expf(fminf(ls[h], LOGIT_MAX));
    p[lane] = v0 * inv;
    p[lane + 32] = v1 * inv;
}

// ---------------------------------------------------------------------------
// Flash attention, fp32 math + paired f16x2 exp. Grid: (N/64, B*H), 256 thr.
// ---------------------------------------------------------------------------
#define QS 68
#define KS 72
#define PS 65

__global__ __launch_bounds__(256) void attn_kernel(
    const float* __restrict__ q, const float* __restrict__ k,
    const float* __restrict__ v, float* __restrict__ x)
{
    extern __shared__ float sm[];
    float* Qs = sm;
    float* Ks = Qs + 64 * QS;
    float* Vs = Ks + 64 * KS;
    float* Ps = Vs + 64 * KS;

    const int tid = threadIdx.x;
    const int r = tid >> 2;
    const int g = tid & 3;
    const int qt = blockIdx.x;
    const int bh = blockIdx.y;
    const int b = bh >> 4, h = bh & 15;
    const int n0 = qt * 64;
    const size_t rs = (size_t)B_ * C_;
    const size_t hb = (size_t)b * C_ + h * HD_;

    const float* qbase = q + hb;
    const float* kbase = k + hb;
    const float* vbase = v + hb;

    for (int idx = tid; idx < 64 * 16; idx += 256) {
        int row = idx >> 4, d4 = idx & 15;
        *(float4*)&Qs[row * QS + d4 * 4] =
            *(const float4*)&qbase[(size_t)(n0 + row) * rs + d4 * 4];
    }

    float4 o0 = {0,0,0,0}, o1 = {0,0,0,0}, o2 = {0,0,0,0}, o3 = {0,0,0,0};
    float mrow = -1e30f, lrow = 0.f;

    for (int kt = 0; kt < 16; kt++) {
        __syncthreads();
        int kn0 = kt * 64;
        for (int idx = tid; idx < 64 * 16; idx += 256) {
            int row = idx >> 4, d4 = idx & 15;
            size_t go = (size_t)(kn0 + row) * rs + d4 * 4;
            *(float4*)&Ks[row * KS + d4 * 4] = *(const float4*)&kbase[go];
            *(float4*)&Vs[row * KS + d4 * 4] = *(const float4*)&vbase[go];
        }
        __syncthreads();

        float s[16];
        #pragma unroll
        for (int j = 0; j < 16; j++) s[j] = 0.f;
        #pragma unroll
        for (int d4 = 0; d4 < 16; d4++) {
            float4 q4 = *(float4*)&Qs[r * QS + d4 * 4];
            #pragma unroll
            for (int j = 0; j < 16; j++) {
                float4 k4 = *(float4*)&Ks[(g + 4 * j) * KS + d4 * 4];
                s[j] += q4.x * k4.x + q4.y * k4.y + q4.z * k4.z + q4.w * k4.w;
            }
        }

        float tmax = s[0];
        #pragma unroll
        for (int j = 1; j < 16; j++) tmax = fmaxf(tmax, s[j]);
        tmax = fmaxf(tmax, __shfl_xor_sync(0xffffffffu, tmax, 1));
        tmax = fmaxf(tmax, __shfl_xor_sync(0xffffffffu, tmax, 2));
        float mnew = fmaxf(mrow, tmax);
        float corr = __expf(mrow - mnew);
        lrow *= corr;
        o0.x *= corr; o0.y *= corr; o0.z *= corr; o0.w *= corr;
        o1.x *= corr; o1.y *= corr; o1.z *= corr; o1.w *= corr;
        o2.x *= corr; o2.y *= corr; o2.z *= corr; o2.w *= corr;
        o3.x *= corr; o3.y *= corr; o3.z *= corr; o3.w *= corr;

        // paired exp: two scores per ex2.approx.f16x2 (halves MUFU pressure)
        float psum = 0.f;
        #pragma unroll
        for (int j = 0; j < 16; j += 2) {
            float t0 = (s[j]     - mnew) * 1.4426950408889634f;
            float t1 = (s[j + 1] - mnew) * 1.4426950408889634f;
            uint32_t pk, er;
            asm("cvt.rn.f16x2.f32 %0, %1, %2;" : "=r"(pk) : "f"(t1), "f"(t0));
            asm("ex2.approx.f16x2 %0, %1;" : "=r"(er) : "r"(pk));
            float p0, p1;
            asm("{ .reg .b16 l, h; mov.b32 {l, h}, %2;"
                " cvt.f32.f16 %0, l; cvt.f32.f16 %1, h; }"
                : "=f"(p0), "=f"(p1) : "r"(er));
            psum += p0 + p1;
            Ps[r * PS + g + 4 * j]       = p0;
            Ps[r * PS + g + 4 * (j + 1)] = p1;
        }
        psum += __shfl_xor_sync(0xffffffffu, psum, 1);
        psum += __shfl_xor_sync(0xffffffffu, psum, 2);
        lrow += psum;
        mrow = mnew;
        __syncwarp();

        #pragma unroll
        for (int j = 0; j < 64; j++) {
            float pv = Ps[r * PS + j];
            const float* vr = &Vs[j * KS + g * 4];
            float4 v0 = *(const float4*)&vr[0];
            float4 v1 = *(const float4*)&vr[16];
            float4 v2 = *(const float4*)&vr[32];
            float4 v3 = *(const float4*)&vr[48];
            o0.x += pv * v0.x; o0.y += pv * v0.y; o0.z += pv * v0.z; o0.w += pv * v0.w;
            o1.x += pv * v1.x; o1.y += pv * v1.y; o1.z += pv * v1.z; o1.w += pv * v1.w;
            o2.x += pv * v2.x; o2.y += pv * v2.y; o2.z += pv * v2.z; o2.w += pv * v2.w;
            o3.x += pv * v3.x; o3.y += pv * v3.y; o3.z += pv * v3.z; o3.w += pv * v3.w;
        }
        __syncwarp();
    }

    float invl = 1.f / lrow;
    float* xb = x + hb + (size_t)(n0 + r) * rs + g * 4;
    float4 w0 = {o0.x*invl, o0.y*invl, o0.z*invl, o0.w*invl};
    float4 w1 = {o1.x*invl, o1.y*invl, o1.z*invl, o1.w*invl};
    float4 w2 = {o2.x*invl, o2.y*invl, o2.z*invl, o2.w*invl};
    float4 w3 = {o3.x*invl, o3.y*invl, o3.z*invl, o3.w*invl};
    *(float4*)&xb[0]  = w0;
    *(float4*)&xb[16] = w1;
    *(float4*)&xb[32] = w2;
    *(float4*)&xb[48] = w3;
}

// ---------------------------------------------------------------------------
// Launcher
// ---------------------------------------------------------------------------
extern "C" void kernel_launch(void* const* d_in, const int* in_sizes, int n_in,
                              void* d_out, int out_size)
{
    const float* query = (const float*)d_in[0];
    const float* key   = (const float*)d_in[1];
    const float* value = (const float*)d_in[2];
    const float* ipw   = (const float*)d_in[3];   // (3C, C)
    const float* ipb   = (const float*)d_in[4];   // (3C)
    const float* ls    = (const float*)d_in[5];   // (H,1,1)
    const float* outw  = (const float*)d_in[6];   // (C, C)
    const float* outb  = (const float*)d_in[7];   // (C)
    float* out = (float*)d_out;

    float *q, *k, *v, *x;
    __nv_bfloat16 *ah, *al, *wh, *wl;
    cudaGetSymbolAddress((void**)&q, g_q);
    cudaGetSymbolAddress((void**)&k, g_k);
    cudaGetSymbolAddress((void**)&v, g_v);
    cudaGetSymbolAddress((void**)&x, g_x);
    cudaGetSymbolAddress((void**)&ah, g_ah);
    cudaGetSymbolAddress((void**)&al, g_al);
    cudaGetSymbolAddress((void**)&wh, g_wh);
    cudaGetSymbolAddress((void**)&wl, g_wl);

    dim3 gg(C_ / GBN, M_ / GBM);   // (8, 32)
    static int gemm_attr_set = 0;
    if (!gemm_attr_set) {
        cudaFuncSetAttribute(gemm_bf16x3_kernel,
                             cudaFuncAttributeMaxDynamicSharedMemorySize, GSMEM);
        gemm_attr_set = 1;
    }

    const int n4_mat = (M_ * C_) / 4;        // 1M float4s per (M x C) matrix
    const int n4_ipw = (3 * C_ * C_) / 4;
    const int n4_ow  = (C_ * C_) / 4;

    // Split weights once per launch
    split_bf16_kernel<<<(n4_ipw + 255)/256, 256>>>(ipw, wh, wl, n4_ipw);
    split_bf16_kernel<<<(n4_ow + 255)/256, 256>>>(outw, wh + (size_t)3*C_*C_,
                                                  wl + (size_t)3*C_*C_, n4_ow);

    // In-projections (A-side split buffer reused serially)
    split_bf16_kernel<<<(n4_mat + 255)/256, 256>>>(query, ah, al, n4_mat);
    gemm_bf16x3_kernel<<<gg, 256, GSMEM>>>(ah, al, wh, wl, ipb, q, M_, C_, C_);

    split_bf16_kernel<<<(n4_mat + 255)/256, 256>>>(key, ah, al, n4_mat);
    gemm_bf16x3_kernel<<<gg, 256, GSMEM>>>(ah, al, wh + (size_t)C_*C_,
                                           wl + (size_t)C_*C_, ipb + C_, k, M_, C_, C_);

    split_bf16_kernel<<<(n4_mat + 255)/256, 256>>>(value, ah, al, n4_mat);
    gemm_bf16x3_kernel<<<gg, 256, GSMEM>>>(ah, al, wh + (size_t)2*C_*C_,
                                           wl + (size_t)2*C_*C_, ipb + 2*C_, v, M_, C_, C_);

    // L2-normalize heads; fold logit scale into q
    norm_kernel<<<(M_ * H_) / 8, 256>>>(q, ls, 1);
    norm_kernel<<<(M_ * H_) / 8, 256>>>(k, ls, 0);

    // Flash attention
    const int smem = (64 * QS + 64 * KS + 64 * KS + 64 * PS) * (int)sizeof(float);
    static int attn_attr_set = 0;
    if (!attn_attr_set) {
        cudaFuncSetAttribute(attn_kernel,
                             cudaFuncAttributeMaxDynamicSharedMemorySize, smem);
        attn_attr_set = 1;
    }
    attn_kernel<<<dim3(N_ / 64, B_ * H_), 256, smem>>>(q, k, v, x);

    // Output projection
    split_bf16_kernel<<<(n4_mat + 255)/256, 256>>>(x, ah, al, n4_mat);
    gemm_bf16x3_kernel<<<gg, 256, GSMEM>>>(ah, al, wh + (size_t)3*C_*C_,
                                           wl + (size_t)3*C_*C_, outb, out, M_, C_, C_);
}

// round 12
// speedup vs baseline: 2.6237x; 2.5308x over previous
#include <cuda_runtime.h>
#include <cuda_bf16.h>
#include <cuda_fp16.h>
#include <math.h>
#include <stdint.h>

// Problem constants
#define N_   1024
#define B_   4
#define C_   1024
#define H_   16
#define HD_  64
#define M_   (N_*B_)
#define LOGIT_MAX 4.6051701859880914f  // log(100)
#define L2E_ 1.4426950408889634f

// Scratch (allocation-free rule: __device__ globals)
__device__ float g_q[M_*C_];
__device__ float g_k[M_*C_];
__device__ float g_v[M_*C_];
__device__ float g_x[M_*C_];
// Pre-split bf16 operands for GEMMs
__device__ __nv_bfloat16 g_ah[M_*C_];
__device__ __nv_bfloat16 g_al[M_*C_];
__device__ __nv_bfloat16 g_wh[4*C_*C_];
__device__ __nv_bfloat16 g_wl[4*C_*C_];
// fp16 split operands for tensor-core attention
__device__ __half g_qh[M_*C_];
__device__ __half g_ql[M_*C_];
__device__ __half g_kh[M_*C_];
__device__ __half g_kl[M_*C_];
__device__ __half g_vh[M_*C_];
__device__ __half g_vl[M_*C_];

// ---------------------------------------------------------------------------
// Common helpers
// ---------------------------------------------------------------------------
__device__ __forceinline__ uint32_t smem_u32(const void* p) {
    uint32_t a;
    asm("{ .reg .u64 t; cvta.to.shared.u64 t, %1; cvt.u32.u64 %0, t; }"
        : "=r"(a) : "l"(p));
    return a;
}
__device__ __forceinline__ void ldsm_x4(uint32_t* r, uint32_t addr) {
    asm volatile("ldmatrix.sync.aligned.m8n8.x4.shared.b16 {%0,%1,%2,%3}, [%4];"
                 : "=r"(r[0]), "=r"(r[1]), "=r"(r[2]), "=r"(r[3]) : "r"(addr));
}
__device__ __forceinline__ void ldsm_x4_t(uint32_t* r, uint32_t addr) {
    asm volatile("ldmatrix.sync.aligned.m8n8.x4.trans.shared.b16 {%0,%1,%2,%3}, [%4];"
                 : "=r"(r[0]), "=r"(r[1]), "=r"(r[2]), "=r"(r[3]) : "r"(addr));
}
__device__ __forceinline__ void mma_bf16(float* c, const uint32_t* a, const uint32_t* b) {
    asm volatile(
        "mma.sync.aligned.m16n8k16.row.col.f32.bf16.bf16.f32 "
        "{%0,%1,%2,%3}, {%4,%5,%6,%7}, {%8,%9}, {%0,%1,%2,%3};"
        : "+f"(c[0]), "+f"(c[1]), "+f"(c[2]), "+f"(c[3])
        : "r"(a[0]), "r"(a[1]), "r"(a[2]), "r"(a[3]), "r"(b[0]), "r"(b[1]));
}
__device__ __forceinline__ void mma_f16(float* c, const uint32_t* a, const uint32_t* b) {
    asm volatile(
        "mma.sync.aligned.m16n8k16.row.col.f32.f16.f16.f32 "
        "{%0,%1,%2,%3}, {%4,%5,%6,%7}, {%8,%9}, {%0,%1,%2,%3};"
        : "+f"(c[0]), "+f"(c[1]), "+f"(c[2]), "+f"(c[3])
        : "r"(a[0]), "r"(a[1]), "r"(a[2]), "r"(a[3]), "r"(b[0]), "r"(b[1]));
}
__device__ __forceinline__ void sts16(uint32_t addr, uint4 v) {
    asm volatile("st.shared.v4.b32 [%0], {%1,%2,%3,%4};" ::
        "r"(addr), "r"(v.x), "r"(v.y), "r"(v.z), "r"(v.w));
}

// ===========================================================================
// Split kernel: fp32 -> bf16 hi + bf16 lo(residual). (GEMM operands)
// ===========================================================================
__global__ __launch_bounds__(256) void split_bf16_kernel(
    const float* __restrict__ src, __nv_bfloat16* __restrict__ hi,
    __nv_bfloat16* __restrict__ lo, int n4)
{
    int i = blockIdx.x * 256 + threadIdx.x;
    if (i >= n4) return;
    float4 f = ((const float4*)src)[i];
    __nv_bfloat16 h0 = __float2bfloat16_rn(f.x);
    __nv_bfloat16 h1 = __float2bfloat16_rn(f.y);
    __nv_bfloat16 h2 = __float2bfloat16_rn(f.z);
    __nv_bfloat16 h3 = __float2bfloat16_rn(f.w);
    __nv_bfloat162 l01 = __floats2bfloat162_rn(f.x - __bfloat162float(h0),
                                               f.y - __bfloat162float(h1));
    __nv_bfloat162 l23 = __floats2bfloat162_rn(f.z - __bfloat162float(h2),
                                               f.w - __bfloat162float(h3));
    __nv_bfloat162 h01; h01.x = h0; h01.y = h1;
    __nv_bfloat162 h23; h23.x = h2; h23.y = h3;
    uint2 hv = { *(uint32_t*)&h01, *(uint32_t*)&h23 };
    uint2 lv = { *(uint32_t*)&l01, *(uint32_t*)&l23 };
    ((uint2*)hi)[i] = hv;
    ((uint2*)lo)[i] = lv;
}

// ===========================================================================
// Split kernel: fp32 -> fp16 hi + fp16 lo(residual). (attention V)
// ===========================================================================
__global__ __launch_bounds__(256) void split_f16_kernel(
    const float* __restrict__ src, __half* __restrict__ hi,
    __half* __restrict__ lo, int n4)
{
    int i = blockIdx.x * 256 + threadIdx.x;
    if (i >= n4) return;
    float4 f = ((const float4*)src)[i];
    __half h0 = __float2half_rn(f.x);
    __half h1 = __float2half_rn(f.y);
    __half h2 = __float2half_rn(f.z);
    __half h3 = __float2half_rn(f.w);
    __half2 hA; hA.x = h0; hA.y = h1;
    __half2 hB; hB.x = h2; hB.y = h3;
    __half2 lA = __floats2half2_rn(f.x - __half2float(h0), f.y - __half2float(h1));
    __half2 lB = __floats2half2_rn(f.z - __half2float(h2), f.w - __half2float(h3));
    uint2 hv = { *(uint32_t*)&hA, *(uint32_t*)&hB };
    uint2 lv = { *(uint32_t*)&lA, *(uint32_t*)&lB };
    ((uint2*)hi)[i] = hv;
    ((uint2*)lo)[i] = lv;
}

// ===========================================================================
// L2-normalize per (row, head), optional logit scale, output fp16 hi/lo split
// ===========================================================================
__global__ __launch_bounds__(256) void normsplit_kernel(
    const float* __restrict__ buf, __half* __restrict__ dh,
    __half* __restrict__ dl, const float* __restrict__ ls, int applyScale)
{
    int gw = (blockIdx.x * 256 + threadIdx.x) >> 5;
    int lane = threadIdx.x & 31;
    if (gw >= M_ * H_) return;
    int m = gw >> 4;
    int h = gw & 15;
    const float* p = buf + (size_t)m * C_ + h * HD_;
    float v0 = p[lane], v1 = p[lane + 32];
    float ss = v0 * v0 + v1 * v1;
    #pragma unroll
    for (int o = 16; o; o >>= 1) ss += __shfl_xor_sync(0xffffffffu, ss, o);
    float inv = rsqrtf(fmaxf(ss, 1e-24f));
    if (applyScale) inv *= __expf(fminf(ls[h], LOGIT_MAX));
    float a0 = v0 * inv, a1 = v1 * inv;
    __half h0 = __float2half_rn(a0), h1 = __float2half_rn(a1);
    size_t o0 = (size_t)m * C_ + h * HD_ + lane;
    dh[o0]      = h0;
    dh[o0 + 32] = h1;
    dl[o0]      = __float2half_rn(a0 - __half2float(h0));
    dl[o0 + 32] = __float2half_rn(a1 - __half2float(h1));
}

// ===========================================================================
// bf16x3 split-precision tensor-core GEMM (unchanged from R10, measured 88.5us)
// ===========================================================================
#define GBM 128
#define GBN 128
#define GBK 32
#define SLABB (128*64)
#define BUFB  (4*SLABB)
#define GSMEM (2*BUFB)

__global__ __launch_bounds__(256) void gemm_bf16x3_kernel(
    const __nv_bfloat16* __restrict__ Ah_g, const __nv_bfloat16* __restrict__ Al_g,
    const __nv_bfloat16* __restrict__ Wh_g, const __nv_bfloat16* __restrict__ Wl_g,
    const float* __restrict__ bias, float* __restrict__ C,
    int M, int N, int K)
{
    extern __shared__ char smem[];
    const uint32_t sbase = smem_u32(smem);
    const int tid  = threadIdx.x;
    const int warp = tid >> 5, lane = tid & 31;
    const int wm = warp >> 2, wn = warp & 3;
    const int m0 = blockIdx.y * GBM, n0 = blockIdx.x * GBN;

    const int prow = tid >> 1, phalf = tid & 1;
    const size_t aoff = (size_t)(m0 + prow) * K + phalf * 16;
    const size_t boff = (size_t)(n0 + prow) * K + phalf * 16;
    const uint32_t xr = (uint32_t)((prow >> 1) & 3);
    const uint32_t rbyte = (uint32_t)prow * 64;
    const uint32_t c0 = (uint32_t)(phalf * 2);
    const uint32_t sa0 = rbyte + ((c0)     ^ xr) * 16;
    const uint32_t sa1 = rbyte + ((c0 + 1) ^ xr) * 16;

    const int a_lrow = lane & 15;
    const uint32_t a_ksel = (uint32_t)(lane >> 4);
    const int b_lrow = ((lane >> 4) << 3) + (lane & 7);
    const uint32_t b_ksel = (uint32_t)((lane >> 3) & 1);

    uint32_t a_off[4], a_xor[4];
    #pragma unroll
    for (int mt = 0; mt < 4; mt++) {
        int r = wm * 64 + mt * 16 + a_lrow;
        a_off[mt] = (uint32_t)r * 64;
        a_xor[mt] = (uint32_t)((r >> 1) & 3);
    }
    uint32_t b_off[2], b_xor[2];
    #pragma unroll
    for (int np = 0; np < 2; np++) {
        int r = wn * 32 + np * 16 + b_lrow;
        b_off[np] = (uint32_t)r * 64;
        b_xor[np] = (uint32_t)((r >> 1) & 3);
    }

    float acc[4][4][4];
    #pragma unroll
    for (int i = 0; i < 4; i++)
        #pragma unroll
        for (int j = 0; j < 4; j++)
            #pragma unroll
            for (int r = 0; r < 4; r++) acc[i][j][r] = 0.f;

    uint4 rAh0, rAh1, rAl0, rAl1, rBh0, rBh1, rBl0, rBl1;

    {
        const __nv_bfloat16* pa = Ah_g + aoff;
        const __nv_bfloat16* pl = Al_g + aoff;
        const __nv_bfloat16* pb = Wh_g + boff;
        const __nv_bfloat16* pw = Wl_g + boff;
        rAh0 = *(const uint4*)pa; rAh1 = *(const uint4*)(pa + 8);
        rAl0 = *(const uint4*)pl; rAl1 = *(const uint4*)(pl + 8);
        rBh0 = *(const uint4*)pb; rBh1 = *(const uint4*)(pb + 8);
        rBl0 = *(const uint4*)pw; rBl1 = *(const uint4*)(pw + 8);
    }
    {
        const uint32_t Ah = sbase, Al = sbase + SLABB;
        const uint32_t Bh = sbase + 2*SLABB, Bl = sbase + 3*SLABB;
        sts16(Ah + sa0, rAh0); sts16(Ah + sa1, rAh1);
        sts16(Al + sa0, rAl0); sts16(Al + sa1, rAl1);
        sts16(Bh + sa0, rBh0); sts16(Bh + sa1, rBh1);
        sts16(Bl + sa0, rBl0); sts16(Bl + sa1, rBl1);
    }
    __syncthreads();

    const int NT = K / GBK;
    for (int t = 0; t < NT; t++) {
        const int buf = t & 1;
        if (t + 1 < NT) {
            const size_t ko = (size_t)(t + 1) * GBK;
            const __nv_bfloat16* pa = Ah_g + aoff + ko;
            const __nv_bfloat16* pl = Al_g + aoff + ko;
            const __nv_bfloat16* pb = Wh_g + boff + ko;
            const __nv_bfloat16* pw = Wl_g + boff + ko;
            rAh0 = *(const uint4*)pa; rAh1 = *(const uint4*)(pa + 8);
            rAl0 = *(const uint4*)pl; rAl1 = *(const uint4*)(pl + 8);
            rBh0 = *(const uint4*)pb; rBh1 = *(const uint4*)(pb + 8);
            rBl0 = *(const uint4*)pw; rBl1 = *(const uint4*)(pw + 8);
        }

        const uint32_t Ah = sbase + buf * BUFB;
        const uint32_t Al = Ah + SLABB;
        const uint32_t Bh = Ah + 2 * SLABB;
        const uint32_t Bl = Ah + 3 * SLABB;

        #pragma unroll
        for (int ks = 0; ks < 2; ks++) {
            uint32_t ah[4][4], al[4][4], bh[2][4], bl[2][4];
            #pragma unroll
            for (int mt = 0; mt < 4; mt++) {
                uint32_t c = (((uint32_t)(ks << 1) + a_ksel) ^ a_xor[mt]) * 16;
                ldsm_x4(ah[mt], Ah + a_off[mt] + c);
                ldsm_x4(al[mt], Al + a_off[mt] + c);
            }
            #pragma unroll
            for (int np = 0; np < 2; np++) {
                uint32_t c = (((uint32_t)(ks << 1) + b_ksel) ^ b_xor[np]) * 16;
                ldsm_x4(bh[np], Bh + b_off[np] + c);
                ldsm_x4(bl[np], Bl + b_off[np] + c);
            }
            #pragma unroll
            for (int mt = 0; mt < 4; mt++)
                #pragma unroll
                for (int nt = 0; nt < 4; nt++) {
                    const uint32_t* bhf = &bh[nt >> 1][(nt & 1) * 2];
                    const uint32_t* blf = &bl[nt >> 1][(nt & 1) * 2];
                    mma_bf16(acc[mt][nt], ah[mt], bhf);
                    mma_bf16(acc[mt][nt], ah[mt], blf);
                    mma_bf16(acc[mt][nt], al[mt], bhf);
                }
        }

        if (t + 1 < NT) {
            const uint32_t nb = sbase + (buf ^ 1) * BUFB;
            sts16(nb + sa0, rAh0);             sts16(nb + sa1, rAh1);
            sts16(nb + SLABB + sa0, rAl0);     sts16(nb + SLABB + sa1, rAl1);
            sts16(nb + 2*SLABB + sa0, rBh0);   sts16(nb + 2*SLABB + sa1, rBh1);
            sts16(nb + 3*SLABB + sa0, rBl0);   sts16(nb + 3*SLABB + sa1, rBl1);
        }
        __syncthreads();
    }

    const int lr = lane >> 2, lc = lane & 3;
    #pragma unroll
    for (int mt = 0; mt < 4; mt++) {
        const int row = m0 + wm * 64 + mt * 16 + lr;
        #pragma unroll
        for (int nt = 0; nt < 4; nt++) {
            const int col = n0 + wn * 32 + nt * 8 + 2 * lc;
            const float bx = bias[col], by = bias[col + 1];
            float2 o0 = { acc[mt][nt][0] + bx, acc[mt][nt][1] + by };
            float2 o1 = { acc[mt][nt][2] + bx, acc[mt][nt][3] + by };
            *(float2*)&C[(size_t)row * N + col]       = o0;
            *(float2*)&C[(size_t)(row + 8) * N + col] = o1;
        }
    }
}

// ===========================================================================
// Tensor-core flash attention (mma.sync f16, fp16x3 QK, fp16x2 PV).
// Grid (N/128, B*H), 256 threads (8 warps x 16 query rows).
// K/V tiles: 64 tokens x 64 dims fp16 hi/lo in smem, 128B rows, 8-chunk XOR
// swizzle by (row&7). P stays in registers: ex2.approx.f16x2 output IS the
// A-fragment of the PV mma (S-frag cols == A-frag k-cols).
// ===========================================================================
__global__ __launch_bounds__(256) void attn_mma_kernel(
    const __half* __restrict__ qh, const __half* __restrict__ ql,
    const __half* __restrict__ kh, const __half* __restrict__ kl,
    const __half* __restrict__ vh, const __half* __restrict__ vl,
    float* __restrict__ x)
{
    __shared__ __align__(1024) uint8_t sm_[32768];
    const uint32_t sb = smem_u32(sm_);
    const uint32_t SKH = 0, SKL = 8192, SVH = 16384, SVL = 24576;
    const int tid = threadIdx.x, w = tid >> 5, lane = tid & 31;
    const int b = blockIdx.y >> 4, h = blockIdx.y & 15;
    const int n0 = blockIdx.x * 128;
    const size_t rs = (size_t)B_ * C_;
    const size_t hb = (size_t)b * C_ + h * 64;

    // ---- stage Q tile: hi at [0,16K), lo at [16K,32K), 128 rows x 128B ----
    {
        int row = tid >> 1;
        int cb  = (tid & 1) * 4;
        const uint4* gh = (const uint4*)(qh + (size_t)(n0 + row) * rs + hb);
        const uint4* gl = (const uint4*)(ql + (size_t)(n0 + row) * rs + hb);
        uint32_t rbase = (uint32_t)row * 128;
        #pragma unroll
        for (int c = 0; c < 4; c++) {
            uint32_t sw = ((uint32_t)((cb + c) ^ (row & 7))) * 16;
            *(uint4*)(sm_ + rbase + sw)         = gh[cb + c];
            *(uint4*)(sm_ + 16384 + rbase + sw) = gl[cb + c];
        }
    }
    __syncthreads();

    // ---- preload Q fragments (A-operand) into registers ----
    uint32_t qfh[4][4], qfl[4][4];
    {
        int arow = w * 16 + (lane & 15);
        uint32_t rbase = (uint32_t)arow * 128;
        #pragma unroll
        for (int ks = 0; ks < 4; ks++) {
            uint32_t c = ((uint32_t)((ks * 2 + (lane >> 4)) ^ (arow & 7))) * 16;
            ldsm_x4(qfh[ks], sb + rbase + c);
            ldsm_x4(qfl[ks], sb + 16384 + rbase + c);
        }
    }

    float oacc[8][4];
    #pragma unroll
    for (int i = 0; i < 8; i++)
        #pragma unroll
        for (int j = 0; j < 4; j++) oacc[i][j] = 0.f;
    float m0 = -1e30f, m1 = -1e30f, l0 = 0.f, l1 = 0.f;

    const int b_lrow = ((lane >> 4) << 3) + (lane & 7);
    const uint32_t b_ksel = (uint32_t)((lane >> 3) & 1);
    const int vg = lane >> 3, vidx = lane & 7;

    for (int kt = 0; kt < 16; kt++) {
        __syncthreads();
        // ---- load K/V hi/lo tiles (64 rows x 128B each slab) ----
        {
            int row = tid >> 2;
            int cc0 = (tid & 3) * 2;
            size_t go = (size_t)(kt * 64 + row) * rs + hb;
            const uint4* gkh = (const uint4*)(kh + go);
            const uint4* gkl = (const uint4*)(kl + go);
            const uint4* gvh = (const uint4*)(vh + go);
            const uint4* gvl = (const uint4*)(vl + go);
            uint32_t rbase = (uint32_t)row * 128;
            #pragma unroll
            for (int c = 0; c < 2; c++) {
                uint32_t sw = ((uint32_t)((cc0 + c) ^ (row & 7))) * 16;
                *(uint4*)(sm_ + SKH + rbase + sw) = gkh[cc0 + c];
                *(uint4*)(sm_ + SKL + rbase + sw) = gkl[cc0 + c];
                *(uint4*)(sm_ + SVH + rbase + sw) = gvh[cc0 + c];
                *(uint4*)(sm_ + SVL + rbase + sw) = gvl[cc0 + c];
            }
        }
        __syncthreads();

        // ---- S = Q K^T (3-pass fp16 split, fp32 accum) ----
        float sacc[8][4];
        #pragma unroll
        for (int i = 0; i < 8; i++)
            #pragma unroll
            for (int j = 0; j < 4; j++) sacc[i][j] = 0.f;

        #pragma unroll
        for (int ks = 0; ks < 4; ks++) {
            uint32_t kfh[4][4], kfl[4][4];
            #pragma unroll
            for (int np = 0; np < 4; np++) {
                int row = np * 16 + b_lrow;
                uint32_t a = (uint32_t)row * 128
                           + ((uint32_t)(ks * 2 + b_ksel) ^ (row & 7)) * 16;
                ldsm_x4(kfh[np], sb + SKH + a);
                ldsm_x4(kfl[np], sb + SKL + a);
            }
            #pragma unroll
            for (int np = 0; np < 4; np++)
                #pragma unroll
                for (int sub = 0; sub < 2; sub++) {
                    int nt = np * 2 + sub;
                    mma_f16(sacc[nt], qfh[ks], &kfh[np][sub * 2]);
                    mma_f16(sacc[nt], qfh[ks], &kfl[np][sub * 2]);
                    mma_f16(sacc[nt], qfl[ks], &kfh[np][sub * 2]);
                }
        }

        // ---- online softmax (two rows per thread: r and r+8) ----
        float tm0 = -1e30f, tm1 = -1e30f;
        #pragma unroll
        for (int nt = 0; nt < 8; nt++) {
            tm0 = fmaxf(tm0, fmaxf(sacc[nt][0], sacc[nt][1]));
            tm1 = fmaxf(tm1, fmaxf(sacc[nt][2], sacc[nt][3]));
        }
        tm0 = fmaxf(tm0, __shfl_xor_sync(0xffffffffu, tm0, 1));
        tm0 = fmaxf(tm0, __shfl_xor_sync(0xffffffffu, tm0, 2));
        tm1 = fmaxf(tm1, __shfl_xor_sync(0xffffffffu, tm1, 1));
        tm1 = fmaxf(tm1, __shfl_xor_sync(0xffffffffu, tm1, 2));
        float mn0 = fmaxf(m0, tm0), mn1 = fmaxf(m1, tm1);
        float cr0 = __expf(m0 - mn0), cr1 = __expf(m1 - mn1);
        l0 *= cr0; l1 *= cr1;
        #pragma unroll
        for (int nt = 0; nt < 8; nt++) {
            oacc[nt][0] *= cr0; oacc[nt][1] *= cr0;
            oacc[nt][2] *= cr1; oacc[nt][3] *= cr1;
        }

        // ---- P = exp(S - m) packed directly into PV A-fragments ----
        uint32_t pA[4][4];
        float ps0 = 0.f, ps1 = 0.f;
        #pragma unroll
        for (int nt = 0; nt < 8; nt++) {
            float t0 = (sacc[nt][0] - mn0) * L2E_;
            float t1 = (sacc[nt][1] - mn0) * L2E_;
            float t2 = (sacc[nt][2] - mn1) * L2E_;
            float t3 = (sacc[nt][3] - mn1) * L2E_;
            uint32_t pk01, e01, pk23, e23;
            asm("cvt.rn.f16x2.f32 %0, %1, %2;" : "=r"(pk01) : "f"(t1), "f"(t0));
            asm("ex2.approx.f16x2 %0, %1;" : "=r"(e01) : "r"(pk01));
            asm("cvt.rn.f16x2.f32 %0, %1, %2;" : "=r"(pk23) : "f"(t3), "f"(t2));
            asm("ex2.approx.f16x2 %0, %1;" : "=r"(e23) : "r"(pk23));
            float f0, f1, f2, f3;
            asm("{ .reg .b16 a, b; mov.b32 {a, b}, %2;"
                " cvt.f32.f16 %0, a; cvt.f32.f16 %1, b; }"
                : "=f"(f0), "=f"(f1) : "r"(e01));
            asm("{ .reg .b16 a, b; mov.b32 {a, b}, %2;"
                " cvt.f32.f16 %0, a; cvt.f32.f16 %1, b; }"
                : "=f"(f2), "=f"(f3) : "r"(e23));
            ps0 += f0 + f1;
            ps1 += f2 + f3;
            int u = nt >> 1, s2 = (nt & 1) * 2;
            pA[u][s2]     = e01;
            pA[u][s2 + 1] = e23;
        }
        ps0 += __shfl_xor_sync(0xffffffffu, ps0, 1);
        ps0 += __shfl_xor_sync(0xffffffffu, ps0, 2);
        ps1 += __shfl_xor_sync(0xffffffffu, ps1, 1);
        ps1 += __shfl_xor_sync(0xffffffffu, ps1, 2);
        l0 += ps0; l1 += ps1;
        m0 = mn0; m1 = mn1;

        // ---- O += P V (V via ldmatrix.trans, hi + lo passes) ----
        #pragma unroll
        for (int ks = 0; ks < 4; ks++) {
            uint32_t vfh[4][4], vfl[4][4];
            int vrow = ks * 16 + (vg & 1) * 8 + vidx;
            #pragma unroll
            for (int hp = 0; hp < 4; hp++) {
                uint32_t a = (uint32_t)vrow * 128
                           + ((uint32_t)(hp * 2 + (vg >> 1)) ^ (vrow & 7)) * 16;
                ldsm_x4_t(vfh[hp], sb + SVH + a);
                ldsm_x4_t(vfl[hp], sb + SVL + a);
            }
            #pragma unroll
            for (int hp = 0; hp < 4; hp++)
                #pragma unroll
                for (int sub = 0; sub < 2; sub++) {
                    int nt = hp * 2 + sub;
                    mma_f16(oacc[nt], pA[ks], &vfh[hp][sub * 2]);
                    mma_f16(oacc[nt], pA[ks], &vfl[hp][sub * 2]);
                }
        }
    }

    // ---- epilogue: divide by l, write fp32 x ----
    float il0 = 1.f / l0, il1 = 1.f / l1;
    int row0 = n0 + w * 16 + (lane >> 2);
    size_t base0 = (size_t)row0 * rs + hb + (lane & 3) * 2;
    #pragma unroll
    for (int nt = 0; nt < 8; nt++) {
        float2 v0 = { oacc[nt][0] * il0, oacc[nt][1] * il0 };
        float2 v1 = { oacc[nt][2] * il1, oacc[nt][3] * il1 };
        *(float2*)&x[base0 + nt * 8]          = v0;
        *(float2*)&x[base0 + 8 * rs + nt * 8] = v1;
    }
}

// ---------------------------------------------------------------------------
// Launcher
// ---------------------------------------------------------------------------
extern "C" void kernel_launch(void* const* d_in, const int* in_sizes, int n_in,
                              void* d_out, int out_size)
{
    const float* query = (const float*)d_in[0];
    const float* key   = (const float*)d_in[1];
    const float* value = (const float*)d_in[2];
    const float* ipw   = (const float*)d_in[3];
    const float* ipb   = (const float*)d_in[4];
    const float* ls    = (const float*)d_in[5];
    const float* outw  = (const float*)d_in[6];
    const float* outb  = (const float*)d_in[7];
    float* out = (float*)d_out;

    float *q, *k, *v, *x;
    __nv_bfloat16 *ah, *al, *wh, *wl;
    __half *qhp, *qlp, *khp, *klp, *vhp, *vlp;
    cudaGetSymbolAddress((void**)&q, g_q);
    cudaGetSymbolAddress((void**)&k, g_k);
    cudaGetSymbolAddress((void**)&v, g_v);
    cudaGetSymbolAddress((void**)&x, g_x);
    cudaGetSymbolAddress((void**)&ah, g_ah);
    cudaGetSymbolAddress((void**)&al, g_al);
    cudaGetSymbolAddress((void**)&wh, g_wh);
    cudaGetSymbolAddress((void**)&wl, g_wl);
    cudaGetSymbolAddress((void**)&qhp, g_qh);
    cudaGetSymbolAddress((void**)&qlp, g_ql);
    cudaGetSymbolAddress((void**)&khp, g_kh);
    cudaGetSymbolAddress((void**)&klp, g_kl);
    cudaGetSymbolAddress((void**)&vhp, g_vh);
    cudaGetSymbolAddress((void**)&vlp, g_vl);

    dim3 gg(C_ / GBN, M_ / GBM);
    static int attr_set = 0;
    if (!attr_set) {
        cudaFuncSetAttribute(gemm_bf16x3_kernel,
                             cudaFuncAttributeMaxDynamicSharedMemorySize, GSMEM);
        attr_set = 1;
    }

    const int n4_mat = (M_ * C_) / 4;
    const int n4_ipw = (3 * C_ * C_) / 4;
    const int n4_ow  = (C_ * C_) / 4;

    // Weights split
    split_bf16_kernel<<<(n4_ipw + 255)/256, 256>>>(ipw, wh, wl, n4_ipw);
    split_bf16_kernel<<<(n4_ow + 255)/256, 256>>>(outw, wh + (size_t)3*C_*C_,
                                                  wl + (size_t)3*C_*C_, n4_ow);

    // In-projections
    split_bf16_kernel<<<(n4_mat + 255)/256, 256>>>(query, ah, al, n4_mat);
    gemm_bf16x3_kernel<<<gg, 256, GSMEM>>>(ah, al, wh, wl, ipb, q, M_, C_, C_);

    split_bf16_kernel<<<(n4_mat + 255)/256, 256>>>(key, ah, al, n4_mat);
    gemm_bf16x3_kernel<<<gg, 256, GSMEM>>>(ah, al, wh + (size_t)C_*C_,
                                           wl + (size_t)C_*C_, ipb + C_, k, M_, C_, C_);

    split_bf16_kernel<<<(n4_mat + 255)/256, 256>>>(value, ah, al, n4_mat);
    gemm_bf16x3_kernel<<<gg, 256, GSMEM>>>(ah, al, wh + (size_t)2*C_*C_,
                                           wl + (size_t)2*C_*C_, ipb + 2*C_, v, M_, C_, C_);

    // Normalize + fp16-split q (with logit scale) and k; split v
    normsplit_kernel<<<(M_ * H_) / 8, 256>>>(q, qhp, qlp, ls, 1);
    normsplit_kernel<<<(M_ * H_) / 8, 256>>>(k, khp, klp, ls, 0);
    split_f16_kernel<<<(n4_mat + 255)/256, 256>>>(v, vhp, vlp, n4_mat);

    // Tensor-core flash attention
    attn_mma_kernel<<<dim3(N_ / 128, B_ * H_), 256>>>(qhp, qlp, khp, klp,
                                                      vhp, vlp, x);

    // Output projection
    split_bf16_kernel<<<(n4_mat + 255)/256, 256>>>(x, ah, al, n4_mat);
    gemm_bf16x3_kernel<<<gg, 256, GSMEM>>>(ah, al, wh + (size_t)3*C_*C_,
                                           wl + (size_t)3*C_*C_, outb, out, M_, C_, C_);
}

// round 13
// speedup vs baseline: 2.6644x; 1.0155x over previous
#include <cuda_runtime.h>
#include <cuda_bf16.h>
#include <cuda_fp16.h>
#include <math.h>
#include <stdint.h>

// Problem constants
#define N_   1024
#define B_   4
#define C_   1024
#define H_   16
#define HD_  64
#define M_   (N_*B_)
#define LOGIT_MAX 4.6051701859880914f  // log(100)
#define L2E_ 1.4426950408889634f

// Scratch (allocation-free rule: __device__ globals)
__device__ float g_q[M_*C_];
__device__ float g_k[M_*C_];
__device__ float g_x_unused[4];          // (x now lives as bf16 split)
// Pre-split bf16 operands for GEMMs
__device__ __nv_bfloat16 g_ah[M_*C_];
__device__ __nv_bfloat16 g_al[M_*C_];
__device__ __nv_bfloat16 g_wh[4*C_*C_];
__device__ __nv_bfloat16 g_wl[4*C_*C_];
// fp16 split operands for tensor-core attention
__device__ __half g_qh[M_*C_];
__device__ __half g_ql[M_*C_];
__device__ __half g_kh[M_*C_];
__device__ __half g_kl[M_*C_];
__device__ __half g_vh[M_*C_];
__device__ __half g_vl[M_*C_];

// ---------------------------------------------------------------------------
// Common helpers
// ---------------------------------------------------------------------------
__device__ __forceinline__ uint32_t smem_u32(const void* p) {
    uint32_t a;
    asm("{ .reg .u64 t; cvta.to.shared.u64 t, %1; cvt.u32.u64 %0, t; }"
        : "=r"(a) : "l"(p));
    return a;
}
__device__ __forceinline__ void ldsm_x4(uint32_t* r, uint32_t addr) {
    asm volatile("ldmatrix.sync.aligned.m8n8.x4.shared.b16 {%0,%1,%2,%3}, [%4];"
                 : "=r"(r[0]), "=r"(r[1]), "=r"(r[2]), "=r"(r[3]) : "r"(addr));
}
__device__ __forceinline__ void ldsm_x4_t(uint32_t* r, uint32_t addr) {
    asm volatile("ldmatrix.sync.aligned.m8n8.x4.trans.shared.b16 {%0,%1,%2,%3}, [%4];"
                 : "=r"(r[0]), "=r"(r[1]), "=r"(r[2]), "=r"(r[3]) : "r"(addr));
}
__device__ __forceinline__ void mma_bf16(float* c, const uint32_t* a, const uint32_t* b) {
    asm volatile(
        "mma.sync.aligned.m16n8k16.row.col.f32.bf16.bf16.f32 "
        "{%0,%1,%2,%3}, {%4,%5,%6,%7}, {%8,%9}, {%0,%1,%2,%3};"
        : "+f"(c[0]), "+f"(c[1]), "+f"(c[2]), "+f"(c[3])
        : "r"(a[0]), "r"(a[1]), "r"(a[2]), "r"(a[3]), "r"(b[0]), "r"(b[1]));
}
__device__ __forceinline__ void mma_f16(float* c, const uint32_t* a, const uint32_t* b) {
    asm volatile(
        "mma.sync.aligned.m16n8k16.row.col.f32.f16.f16.f32 "
        "{%0,%1,%2,%3}, {%4,%5,%6,%7}, {%8,%9}, {%0,%1,%2,%3};"
        : "+f"(c[0]), "+f"(c[1]), "+f"(c[2]), "+f"(c[3])
        : "r"(a[0]), "r"(a[1]), "r"(a[2]), "r"(a[3]), "r"(b[0]), "r"(b[1]));
}
__device__ __forceinline__ void cp_async16(uint32_t saddr, const void* gptr) {
    asm volatile("cp.async.cg.shared.global [%0], [%1], 16;"
                 :: "r"(saddr), "l"(gptr));
}
#define CP_COMMIT() asm volatile("cp.async.commit_group;" ::: "memory")
#define CP_WAIT0()  asm volatile("cp.async.wait_group 0;" ::: "memory")

// ===========================================================================
// Split kernels (grid-stride, 2 float4 per thread iter)
// ===========================================================================
__global__ __launch_bounds__(256) void split_bf16_kernel(
    const float* __restrict__ src, __nv_bfloat16* __restrict__ hi,
    __nv_bfloat16* __restrict__ lo, int n4)
{
    for (int i = blockIdx.x * 256 + threadIdx.x; i < n4; i += gridDim.x * 256) {
        float4 f = ((const float4*)src)[i];
        __nv_bfloat16 h0 = __float2bfloat16_rn(f.x);
        __nv_bfloat16 h1 = __float2bfloat16_rn(f.y);
        __nv_bfloat16 h2 = __float2bfloat16_rn(f.z);
        __nv_bfloat16 h3 = __float2bfloat16_rn(f.w);
        __nv_bfloat162 l01 = __floats2bfloat162_rn(f.x - __bfloat162float(h0),
                                                   f.y - __bfloat162float(h1));
        __nv_bfloat162 l23 = __floats2bfloat162_rn(f.z - __bfloat162float(h2),
                                                   f.w - __bfloat162float(h3));
        __nv_bfloat162 h01; h01.x = h0; h01.y = h1;
        __nv_bfloat162 h23; h23.x = h2; h23.y = h3;
        uint2 hv = { *(uint32_t*)&h01, *(uint32_t*)&h23 };
        uint2 lv = { *(uint32_t*)&l01, *(uint32_t*)&l23 };
        ((uint2*)hi)[i] = hv;
        ((uint2*)lo)[i] = lv;
    }
}

// ===========================================================================
// L2-normalize per (row, head), optional logit scale, output fp16 hi/lo split
// ===========================================================================
__global__ __launch_bounds__(256) void normsplit_kernel(
    const float* __restrict__ buf, __half* __restrict__ dh,
    __half* __restrict__ dl, const float* __restrict__ ls, int applyScale)
{
    int gw = (blockIdx.x * 256 + threadIdx.x) >> 5;
    int lane = threadIdx.x & 31;
    if (gw >= M_ * H_) return;
    int m = gw >> 4;
    int h = gw & 15;
    const float* p = buf + (size_t)m * C_ + h * HD_;
    float v0 = p[lane], v1 = p[lane + 32];
    float ss = v0 * v0 + v1 * v1;
    #pragma unroll
    for (int o = 16; o; o >>= 1) ss += __shfl_xor_sync(0xffffffffu, ss, o);
    float inv = rsqrtf(fmaxf(ss, 1e-24f));
    if (applyScale) inv *= __expf(fminf(ls[h], LOGIT_MAX));
    float a0 = v0 * inv, a1 = v1 * inv;
    __half h0 = __float2half_rn(a0), h1 = __float2half_rn(a1);
    size_t o0 = (size_t)m * C_ + h * HD_ + lane;
    dh[o0]      = h0;
    dh[o0 + 32] = h1;
    dl[o0]      = __float2half_rn(a0 - __half2float(h0));
    dl[o0 + 32] = __float2half_rn(a1 - __half2float(h1));
}

// ===========================================================================
// bf16x3 split-precision tensor-core GEMM, cp.async staged, 2 CTAs/SM.
//   mode 0: C = fp32 out.  mode 1: fp16 hi/lo out (H1, H2); C unused.
// ===========================================================================
#define GBM 128
#define GBN 128
#define GBK 32
#define SLABB (128*64)
#define BUFB  (4*SLABB)
#define GSMEM (2*BUFB)

__global__ __launch_bounds__(256, 2) void gemm_bf16x3_kernel(
    const __nv_bfloat16* __restrict__ Ah_g, const __nv_bfloat16* __restrict__ Al_g,
    const __nv_bfloat16* __restrict__ Wh_g, const __nv_bfloat16* __restrict__ Wl_g,
    const float* __restrict__ bias, float* __restrict__ C,
    __half* __restrict__ H1, __half* __restrict__ H2, int mode,
    int M, int N, int K)
{
    extern __shared__ char smem[];
    const uint32_t sbase = smem_u32(smem);
    const int tid  = threadIdx.x;
    const int warp = tid >> 5, lane = tid & 31;
    const int wm = warp >> 2, wn = warp & 3;
    const int m0 = blockIdx.y * GBM, n0 = blockIdx.x * GBN;

    // producer strip: row = tid/2, k-half = tid&1
    const int prow = tid >> 1, phalf = tid & 1;
    const size_t aoff = (size_t)(m0 + prow) * K + phalf * 16;
    const size_t boff = (size_t)(n0 + prow) * K + phalf * 16;
    const uint32_t xr = (uint32_t)((prow >> 1) & 3);
    const uint32_t rbyte = (uint32_t)prow * 64;
    const uint32_t c0 = (uint32_t)(phalf * 2);
    const uint32_t sa0 = rbyte + ((c0)     ^ xr) * 16;
    const uint32_t sa1 = rbyte + ((c0 + 1) ^ xr) * 16;

    // fragment address bases (xor is mt/np independent — only lane-row bits)
    const int a_lrow = lane & 15;
    const uint32_t a_ksel = (uint32_t)(lane >> 4);
    const uint32_t a_xor = (uint32_t)((a_lrow >> 1) & 3);
    const uint32_t a_rb = (uint32_t)(wm * 64 + a_lrow) * 64;
    const int b_lrow = ((lane >> 4) << 3) + (lane & 7);
    const uint32_t b_ksel = (uint32_t)((lane >> 3) & 1);
    const uint32_t b_xor = (uint32_t)((b_lrow >> 1) & 3);
    const uint32_t b_rb = (uint32_t)(wn * 32 + b_lrow) * 64;

    float acc[4][4][4];
    #pragma unroll
    for (int i = 0; i < 4; i++)
        #pragma unroll
        for (int j = 0; j < 4; j++)
            #pragma unroll
            for (int r = 0; r < 4; r++) acc[i][j][r] = 0.f;

    // prologue: stage tile 0 into buffer 0 via cp.async
    {
        const uint32_t nb = sbase;
        cp_async16(nb + sa0,             Ah_g + aoff);
        cp_async16(nb + sa1,             Ah_g + aoff + 8);
        cp_async16(nb + SLABB + sa0,     Al_g + aoff);
        cp_async16(nb + SLABB + sa1,     Al_g + aoff + 8);
        cp_async16(nb + 2*SLABB + sa0,   Wh_g + boff);
        cp_async16(nb + 2*SLABB + sa1,   Wh_g + boff + 8);
        cp_async16(nb + 3*SLABB + sa0,   Wl_g + boff);
        cp_async16(nb + 3*SLABB + sa1,   Wl_g + boff + 8);
        CP_COMMIT();
    }

    const int NT = K / GBK;
    for (int t = 0; t < NT; t++) {
        const int buf = t & 1;
        CP_WAIT0();
        __syncthreads();

        if (t + 1 < NT) {
            const size_t ko = (size_t)(t + 1) * GBK;
            const uint32_t nb = sbase + (buf ^ 1) * BUFB;
            cp_async16(nb + sa0,             Ah_g + aoff + ko);
            cp_async16(nb + sa1,             Ah_g + aoff + ko + 8);
            cp_async16(nb + SLABB + sa0,     Al_g + aoff + ko);
            cp_async16(nb + SLABB + sa1,     Al_g + aoff + ko + 8);
            cp_async16(nb + 2*SLABB + sa0,   Wh_g + boff + ko);
            cp_async16(nb + 2*SLABB + sa1,   Wh_g + boff + ko + 8);
            cp_async16(nb + 3*SLABB + sa0,   Wl_g + boff + ko);
            cp_async16(nb + 3*SLABB + sa1,   Wl_g + boff + ko + 8);
            CP_COMMIT();
        }

        const uint32_t Ahb = sbase + buf * BUFB + a_rb;
        const uint32_t Bhb = sbase + buf * BUFB + 2 * SLABB + b_rb;

        #pragma unroll
        for (int ks = 0; ks < 2; ks++) {
            uint32_t ah[4][4], al[4][4], bh[2][4], bl[2][4];
            const uint32_t ca = (((uint32_t)(ks << 1) + a_ksel) ^ a_xor) * 16;
            const uint32_t cb = (((uint32_t)(ks << 1) + b_ksel) ^ b_xor) * 16;
            #pragma unroll
            for (int mt = 0; mt < 4; mt++) {
                ldsm_x4(ah[mt], Ahb + mt * 1024 + ca);
                ldsm_x4(al[mt], Ahb + SLABB + mt * 1024 + ca);
            }
            #pragma unroll
            for (int np = 0; np < 2; np++) {
                ldsm_x4(bh[np], Bhb + np * 1024 + cb);
                ldsm_x4(bl[np], Bhb + SLABB + np * 1024 + cb);
            }
            #pragma unroll
            for (int mt = 0; mt < 4; mt++)
                #pragma unroll
                for (int nt = 0; nt < 4; nt++) {
                    const uint32_t* bhf = &bh[nt >> 1][(nt & 1) * 2];
                    const uint32_t* blf = &bl[nt >> 1][(nt & 1) * 2];
                    mma_bf16(acc[mt][nt], ah[mt], bhf);
                    mma_bf16(acc[mt][nt], ah[mt], blf);
                    mma_bf16(acc[mt][nt], al[mt], bhf);
                }
        }
        __syncthreads();
    }

    // Epilogue
    const int lr = lane >> 2, lc = lane & 3;
    #pragma unroll
    for (int mt = 0; mt < 4; mt++) {
        const int row = m0 + wm * 64 + mt * 16 + lr;
        #pragma unroll
        for (int nt = 0; nt < 4; nt++) {
            const int col = n0 + wn * 32 + nt * 8 + 2 * lc;
            const float bx = bias[col], by = bias[col + 1];
            float v00 = acc[mt][nt][0] + bx, v01 = acc[mt][nt][1] + by;
            float v10 = acc[mt][nt][2] + bx, v11 = acc[mt][nt][3] + by;
            if (mode == 0) {
                float2 o0 = { v00, v01 };
                float2 o1 = { v10, v11 };
                *(float2*)&C[(size_t)row * N + col]       = o0;
                *(float2*)&C[(size_t)(row + 8) * N + col] = o1;
            } else {
                __half h00 = __float2half_rn(v00), h01 = __float2half_rn(v01);
                __half h10 = __float2half_rn(v10), h11 = __float2half_rn(v11);
                __half2 hp0; hp0.x = h00; hp0.y = h01;
                __half2 hp1; hp1.x = h10; hp1.y = h11;
                __half2 lp0 = __floats2half2_rn(v00 - __half2float(h00),
                                                v01 - __half2float(h01));
                __half2 lp1 = __floats2half2_rn(v10 - __half2float(h10),
                                                v11 - __half2float(h11));
                *(__half2*)&H1[(size_t)row * N + col]       = hp0;
                *(__half2*)&H1[(size_t)(row + 8) * N + col] = hp1;
                *(__half2*)&H2[(size_t)row * N + col]       = lp0;
                *(__half2*)&H2[(size_t)(row + 8) * N + col] = lp1;
            }
        }
    }
}

// ===========================================================================
// Tensor-core flash attention (unchanged core from R12; epilogue now emits
// bf16 hi/lo split of x directly for the out-projection).
// ===========================================================================
__global__ __launch_bounds__(256) void attn_mma_kernel(
    const __half* __restrict__ qh, const __half* __restrict__ ql,
    const __half* __restrict__ kh, const __half* __restrict__ kl,
    const __half* __restrict__ vh, const __half* __restrict__ vl,
    __nv_bfloat16* __restrict__ xh, __nv_bfloat16* __restrict__ xl)
{
    __shared__ __align__(1024) uint8_t sm_[32768];
    const uint32_t sb = smem_u32(sm_);
    const uint32_t SKH = 0, SKL = 8192, SVH = 16384, SVL = 24576;
    const int tid = threadIdx.x, w = tid >> 5, lane = tid & 31;
    const int b = blockIdx.y >> 4, h = blockIdx.y & 15;
    const int n0 = blockIdx.x * 128;
    const size_t rs = (size_t)B_ * C_;
    const size_t hb = (size_t)b * C_ + h * 64;

    // stage Q tile (hi [0,16K), lo [16K,32K))
    {
        int row = tid >> 1;
        int cb  = (tid & 1) * 4;
        const uint4* gh = (const uint4*)(qh + (size_t)(n0 + row) * rs + hb);
        const uint4* gl = (const uint4*)(ql + (size_t)(n0 + row) * rs + hb);
        uint32_t rbase = (uint32_t)row * 128;
        #pragma unroll
        for (int c = 0; c < 4; c++) {
            uint32_t sw = ((uint32_t)((cb + c) ^ (row & 7))) * 16;
            *(uint4*)(sm_ + rbase + sw)         = gh[cb + c];
            *(uint4*)(sm_ + 16384 + rbase + sw) = gl[cb + c];
        }
    }
    __syncthreads();

    uint32_t qfh[4][4], qfl[4][4];
    {
        int arow = w * 16 + (lane & 15);
        uint32_t rbase = (uint32_t)arow * 128;
        #pragma unroll
        for (int ks = 0; ks < 4; ks++) {
            uint32_t c = ((uint32_t)((ks * 2 + (lane >> 4)) ^ (arow & 7))) * 16;
            ldsm_x4(qfh[ks], sb + rbase + c);
            ldsm_x4(qfl[ks], sb + 16384 + rbase + c);
        }
    }

    float oacc[8][4];
    #pragma unroll
    for (int i = 0; i < 8; i++)
        #pragma unroll
        for (int j = 0; j < 4; j++) oacc[i][j] = 0.f;
    float m0 = -1e30f, m1 = -1e30f, l0 = 0.f, l1 = 0.f;

    const int b_lrow = ((lane >> 4) << 3) + (lane & 7);
    const uint32_t b_ksel = (uint32_t)((lane >> 3) & 1);
    const int vg = lane >> 3, vidx = lane & 7;

    for (int kt = 0; kt < 16; kt++) {
        __syncthreads();
        {
            int row = tid >> 2;
            int cc0 = (tid & 3) * 2;
            size_t go = (size_t)(kt * 64 + row) * rs + hb;
            const uint4* gkh = (const uint4*)(kh + go);
            const uint4* gkl = (const uint4*)(kl + go);
            const uint4* gvh = (const uint4*)(vh + go);
            const uint4* gvl = (const uint4*)(vl + go);
            uint32_t rbase = (uint32_t)row * 128;
            #pragma unroll
            for (int c = 0; c < 2; c++) {
                uint32_t sw = ((uint32_t)((cc0 + c) ^ (row & 7))) * 16;
                *(uint4*)(sm_ + SKH + rbase + sw) = gkh[cc0 + c];
                *(uint4*)(sm_ + SKL + rbase + sw) = gkl[cc0 + c];
                *(uint4*)(sm_ + SVH + rbase + sw) = gvh[cc0 + c];
                *(uint4*)(sm_ + SVL + rbase + sw) = gvl[cc0 + c];
            }
        }
        __syncthreads();

        float sacc[8][4];
        #pragma unroll
        for (int i = 0; i < 8; i++)
            #pragma unroll
            for (int j = 0; j < 4; j++) sacc[i][j] = 0.f;

        #pragma unroll
        for (int ks = 0; ks < 4; ks++) {
            uint32_t kfh[4][4], kfl[4][4];
            #pragma unroll
            for (int np = 0; np < 4; np++) {
                int row = np * 16 + b_lrow;
                uint32_t a = (uint32_t)row * 128
                           + ((uint32_t)(ks * 2 + b_ksel) ^ (row & 7)) * 16;
                ldsm_x4(kfh[np], sb + SKH + a);
                ldsm_x4(kfl[np], sb + SKL + a);
            }
            #pragma unroll
            for (int np = 0; np < 4; np++)
                #pragma unroll
                for (int sub = 0; sub < 2; sub++) {
                    int nt = np * 2 + sub;
                    mma_f16(sacc[nt], qfh[ks], &kfh[np][sub * 2]);
                    mma_f16(sacc[nt], qfh[ks], &kfl[np][sub * 2]);
                    mma_f16(sacc[nt], qfl[ks], &kfh[np][sub * 2]);
                }
        }

        float tm0 = -1e30f, tm1 = -1e30f;
        #pragma unroll
        for (int nt = 0; nt < 8; nt++) {
            tm0 = fmaxf(tm0, fmaxf(sacc[nt][0], sacc[nt][1]));
            tm1 = fmaxf(tm1, fmaxf(sacc[nt][2], sacc[nt][3]));
        }
        tm0 = fmaxf(tm0, __shfl_xor_sync(0xffffffffu, tm0, 1));
        tm0 = fmaxf(tm0, __shfl_xor_sync(0xffffffffu, tm0, 2));
        tm1 = fmaxf(tm1, __shfl_xor_sync(0xffffffffu, tm1, 1));
        tm1 = fmaxf(tm1, __shfl_xor_sync(0xffffffffu, tm1, 2));
        float mn0 = fmaxf(m0, tm0), mn1 = fmaxf(m1, tm1);
        float cr0 = __expf(m0 - mn0), cr1 = __expf(m1 - mn1);
        l0 *= cr0; l1 *= cr1;
        #pragma unroll
        for (int nt = 0; nt < 8; nt++) {
            oacc[nt][0] *= cr0; oacc[nt][1] *= cr0;
            oacc[nt][2] *= cr1; oacc[nt][3] *= cr1;
        }

        uint32_t pA[4][4];
        float ps0 = 0.f, ps1 = 0.f;
        #pragma unroll
        for (int nt = 0; nt < 8; nt++) {
            float t0 = (sacc[nt][0] - mn0) * L2E_;
            float t1 = (sacc[nt][1] - mn0) * L2E_;
            float t2 = (sacc[nt][2] - mn1) * L2E_;
            float t3 = (sacc[nt][3] - mn1) * L2E_;
            uint32_t pk01, e01, pk23, e23;
            asm("cvt.rn.f16x2.f32 %0, %1, %2;" : "=r"(pk01) : "f"(t1), "f"(t0));
            asm("ex2.approx.f16x2 %0, %1;" : "=r"(e01) : "r"(pk01));
            asm("cvt.rn.f16x2.f32 %0, %1, %2;" : "=r"(pk23) : "f"(t3), "f"(t2));
            asm("ex2.approx.f16x2 %0, %1;" : "=r"(e23) : "r"(pk23));
            float f0, f1, f2, f3;
            asm("{ .reg .b16 a, b; mov.b32 {a, b}, %2;"
                " cvt.f32.f16 %0, a; cvt.f32.f16 %1, b; }"
                : "=f"(f0), "=f"(f1) : "r"(e01));
            asm("{ .reg .b16 a, b; mov.b32 {a, b}, %2;"
                " cvt.f32.f16 %0, a; cvt.f32.f16 %1, b; }"
                : "=f"(f2), "=f"(f3) : "r"(e23));
            ps0 += f0 + f1;
            ps1 += f2 + f3;
            int u = nt >> 1, s2 = (nt & 1) * 2;
            pA[u][s2]     = e01;
            pA[u][s2 + 1] = e23;
        }
        ps0 += __shfl_xor_sync(0xffffffffu, ps0, 1);
        ps0 += __shfl_xor_sync(0xffffffffu, ps0, 2);
        ps1 += __shfl_xor_sync(0xffffffffu, ps1, 1);
        ps1 += __shfl_xor_sync(0xffffffffu, ps1, 2);
        l0 += ps0; l1 += ps1;
        m0 = mn0; m1 = mn1;

        #pragma unroll
        for (int ks = 0; ks < 4; ks++) {
            uint32_t vfh[4][4], vfl[4][4];
            int vrow = ks * 16 + (vg & 1) * 8 + vidx;
            #pragma unroll
            for (int hp = 0; hp < 4; hp++) {
                uint32_t a = (uint32_t)vrow * 128
                           + ((uint32_t)(hp * 2 + (vg >> 1)) ^ (vrow & 7)) * 16;
                ldsm_x4_t(vfh[hp], sb + SVH + a);
                ldsm_x4_t(vfl[hp], sb + SVL + a);
            }
            #pragma unroll
            for (int hp = 0; hp < 4; hp++)
                #pragma unroll
                for (int sub = 0; sub < 2; sub++) {
                    int nt = hp * 2 + sub;
                    mma_f16(oacc[nt], pA[ks], &vfh[hp][sub * 2]);
                    mma_f16(oacc[nt], pA[ks], &vfl[hp][sub * 2]);
                }
        }
    }

    // epilogue: divide by l, emit bf16 hi/lo split of x
    float il0 = 1.f / l0, il1 = 1.f / l1;
    int row0 = n0 + w * 16 + (lane >> 2);
    size_t base0 = (size_t)row0 * rs + hb + (lane & 3) * 2;
    #pragma unroll
    for (int nt = 0; nt < 8; nt++) {
        float a0 = oacc[nt][0] * il0, a1 = oacc[nt][1] * il0;
        float b0 = oacc[nt][2] * il1, b1 = oacc[nt][3] * il1;
        __nv_bfloat16 h0 = __float2bfloat16_rn(a0), h1 = __float2bfloat16_rn(a1);
        __nv_bfloat16 g0 = __float2bfloat16_rn(b0), g1 = __float2bfloat16_rn(b1);
        __nv_bfloat162 hp0; hp0.x = h0; hp0.y = h1;
        __nv_bfloat162 hp1; hp1.x = g0; hp1.y = g1;
        __nv_bfloat162 lp0 = __floats2bfloat162_rn(a0 - __bfloat162float(h0),
                                                   a1 - __bfloat162float(h1));
        __nv_bfloat162 lp1 = __floats2bfloat162_rn(b0 - __bfloat162float(g0),
                                                   b1 - __bfloat162float(g1));
        *(__nv_bfloat162*)&xh[base0 + nt * 8]          = hp0;
        *(__nv_bfloat162*)&xh[base0 + 8 * rs + nt * 8] = hp1;
        *(__nv_bfloat162*)&xl[base0 + nt * 8]          = lp0;
        *(__nv_bfloat162*)&xl[base0 + 8 * rs + nt * 8] = lp1;
    }
}

// ---------------------------------------------------------------------------
// Launcher
// ---------------------------------------------------------------------------
extern "C" void kernel_launch(void* const* d_in, const int* in_sizes, int n_in,
                              void* d_out, int out_size)
{
    const float* query = (const float*)d_in[0];
    const float* key   = (const float*)d_in[1];
    const float* value = (const float*)d_in[2];
    const float* ipw   = (const float*)d_in[3];
    const float* ipb   = (const float*)d_in[4];
    const float* ls    = (const float*)d_in[5];
    const float* outw  = (const float*)d_in[6];
    const float* outb  = (const float*)d_in[7];
    float* out = (float*)d_out;

    float *q, *k;
    __nv_bfloat16 *ah, *al, *wh, *wl;
    __half *qhp, *qlp, *khp, *klp, *vhp, *vlp;
    cudaGetSymbolAddress((void**)&q, g_q);
    cudaGetSymbolAddress((void**)&k, g_k);
    cudaGetSymbolAddress((void**)&ah, g_ah);
    cudaGetSymbolAddress((void**)&al, g_al);
    cudaGetSymbolAddress((void**)&wh, g_wh);
    cudaGetSymbolAddress((void**)&wl, g_wl);
    cudaGetSymbolAddress((void**)&qhp, g_qh);
    cudaGetSymbolAddress((void**)&qlp, g_ql);
    cudaGetSymbolAddress((void**)&khp, g_kh);
    cudaGetSymbolAddress((void**)&klp, g_kl);
    cudaGetSymbolAddress((void**)&vhp, g_vh);
    cudaGetSymbolAddress((void**)&vlp, g_vl);

    dim3 gg(C_ / GBN, M_ / GBM);
    static int attr_set = 0;
    if (!attr_set) {
        cudaFuncSetAttribute(gemm_bf16x3_kernel,
                             cudaFuncAttributeMaxDynamicSharedMemorySize, GSMEM);
        attr_set = 1;
    }

    const int n4_mat = (M_ * C_) / 4;
    const int n4_ipw = (3 * C_ * C_) / 4;
    const int n4_ow  = (C_ * C_) / 4;

    // Weight splits
    split_bf16_kernel<<<1184, 256>>>(ipw, wh, wl, n4_ipw);
    split_bf16_kernel<<<592, 256>>>(outw, wh + (size_t)3*C_*C_,
                                    wl + (size_t)3*C_*C_, n4_ow);

    // In-projections (q, k to fp32 for normsplit; v straight to fp16 split)
    split_bf16_kernel<<<1184, 256>>>(query, ah, al, n4_mat);
    gemm_bf16x3_kernel<<<gg, 256, GSMEM>>>(ah, al, wh, wl, ipb,
                                           q, (__half*)0, (__half*)0, 0, M_, C_, C_);

    split_bf16_kernel<<<1184, 256>>>(key, ah, al, n4_mat);
    gemm_bf16x3_kernel<<<gg, 256, GSMEM>>>(ah, al, wh + (size_t)C_*C_,
                                           wl + (size_t)C_*C_, ipb + C_,
                                           k, (__half*)0, (__half*)0, 0, M_, C_, C_);

    split_bf16_kernel<<<1184, 256>>>(value, ah, al, n4_mat);
    gemm_bf16x3_kernel<<<gg, 256, GSMEM>>>(ah, al, wh + (size_t)2*C_*C_,
                                           wl + (size_t)2*C_*C_, ipb + 2*C_,
                                           (float*)0, vhp, vlp, 1, M_, C_, C_);

    // Normalize + fp16-split q (with logit scale) and k
    normsplit_kernel<<<(M_ * H_) / 8, 256>>>(q, qhp, qlp, ls, 1);
    normsplit_kernel<<<(M_ * H_) / 8, 256>>>(k, khp, klp, ls, 0);

    // Tensor-core flash attention -> bf16 split x (reuses ah/al)
    attn_mma_kernel<<<dim3(N_ / 128, B_ * H_), 256>>>(qhp, qlp, khp, klp,
                                                      vhp, vlp, ah, al);

    // Output projection
    gemm_bf16x3_kernel<<<gg, 256, GSMEM>>>(ah, al, wh + (size_t)3*C_*C_,
                                           wl + (size_t)3*C_*C_, outb,
                                           out, (__half*)0, (__half*)0, 0, M_, C_, C_);
}

// round 15
// speedup vs baseline: 2.6980x; 1.0126x over previous
#include <cuda_runtime.h>
#include <cuda_bf16.h>
#include <cuda_fp16.h>
#include <math.h>
#include <stdint.h>

// Problem constants
#define N_   1024
#define B_   4
#define C_   1024
#define H_   16
#define HD_  64
#define M_   (N_*B_)
#define LOGIT_MAX 4.6051701859880914f  // log(100)
#define L2E_ 1.4426950408889634f

// Scratch (allocation-free rule: __device__ globals)
__device__ float g_q[M_*C_];
__device__ float g_k[M_*C_];
// Pre-split bf16 operands for GEMMs (3 A-slices for fused QKV; slice 0 reused for x)
__device__ __nv_bfloat16 g_ah[3*M_*C_];
__device__ __nv_bfloat16 g_al[3*M_*C_];
__device__ __nv_bfloat16 g_wh[4*C_*C_];
__device__ __nv_bfloat16 g_wl[4*C_*C_];
// fp16 split operands for tensor-core attention
__device__ __half g_qh[M_*C_];
__device__ __half g_ql[M_*C_];
__device__ __half g_kh[M_*C_];
__device__ __half g_kl[M_*C_];
__device__ __half g_vh[M_*C_];
__device__ __half g_vl[M_*C_];

// ---------------------------------------------------------------------------
// Common helpers
// ---------------------------------------------------------------------------
__device__ __forceinline__ uint32_t smem_u32(const void* p) {
    uint32_t a;
    asm("{ .reg .u64 t; cvta.to.shared.u64 t, %1; cvt.u32.u64 %0, t; }"
        : "=r"(a) : "l"(p));
    return a;
}
__device__ __forceinline__ void ldsm_x4(uint32_t* r, uint32_t addr) {
    asm volatile("ldmatrix.sync.aligned.m8n8.x4.shared.b16 {%0,%1,%2,%3}, [%4];"
                 : "=r"(r[0]), "=r"(r[1]), "=r"(r[2]), "=r"(r[3]) : "r"(addr));
}
__device__ __forceinline__ void ldsm_x4_t(uint32_t* r, uint32_t addr) {
    asm volatile("ldmatrix.sync.aligned.m8n8.x4.trans.shared.b16 {%0,%1,%2,%3}, [%4];"
                 : "=r"(r[0]), "=r"(r[1]), "=r"(r[2]), "=r"(r[3]) : "r"(addr));
}
__device__ __forceinline__ void mma_bf16(float* c, const uint32_t* a, const uint32_t* b) {
    asm volatile(
        "mma.sync.aligned.m16n8k16.row.col.f32.bf16.bf16.f32 "
        "{%0,%1,%2,%3}, {%4,%5,%6,%7}, {%8,%9}, {%0,%1,%2,%3};"
        : "+f"(c[0]), "+f"(c[1]), "+f"(c[2]), "+f"(c[3])
        : "r"(a[0]), "r"(a[1]), "r"(a[2]), "r"(a[3]), "r"(b[0]), "r"(b[1]));
}
__device__ __forceinline__ void mma_f16(float* c, const uint32_t* a, const uint32_t* b) {
    asm volatile(
        "mma.sync.aligned.m16n8k16.row.col.f32.f16.f16.f32 "
        "{%0,%1,%2,%3}, {%4,%5,%6,%7}, {%8,%9}, {%0,%1,%2,%3};"
        : "+f"(c[0]), "+f"(c[1]), "+f"(c[2]), "+f"(c[3])
        : "r"(a[0]), "r"(a[1]), "r"(a[2]), "r"(a[3]), "r"(b[0]), "r"(b[1]));
}
__device__ __forceinline__ void cp_async16(uint32_t saddr, const void* gptr) {
    asm volatile("cp.async.cg.shared.global [%0], [%1], 16;"
                 :: "r"(saddr), "l"(gptr));
}
#define CP_COMMIT() asm volatile("cp.async.commit_group;" ::: "memory")
#define CP_WAIT0()  asm volatile("cp.async.wait_group 0;" ::: "memory")
#define CP_WAIT1()  asm volatile("cp.async.wait_group 1;" ::: "memory")

// ===========================================================================
// Split kernel: fp32 -> bf16 hi + bf16 lo(residual). (grid-stride)
// ===========================================================================
__global__ __launch_bounds__(256) void split_bf16_kernel(
    const float* __restrict__ src, __nv_bfloat16* __restrict__ hi,
    __nv_bfloat16* __restrict__ lo, int n4)
{
    for (int i = blockIdx.x * 256 + threadIdx.x; i < n4; i += gridDim.x * 256) {
        float4 f = ((const float4*)src)[i];
        __nv_bfloat16 h0 = __float2bfloat16_rn(f.x);
        __nv_bfloat16 h1 = __float2bfloat16_rn(f.y);
        __nv_bfloat16 h2 = __float2bfloat16_rn(f.z);
        __nv_bfloat16 h3 = __float2bfloat16_rn(f.w);
        __nv_bfloat162 l01 = __floats2bfloat162_rn(f.x - __bfloat162float(h0),
                                                   f.y - __bfloat162float(h1));
        __nv_bfloat162 l23 = __floats2bfloat162_rn(f.z - __bfloat162float(h2),
                                                   f.w - __bfloat162float(h3));
        __nv_bfloat162 h01; h01.x = h0; h01.y = h1;
        __nv_bfloat162 h23; h23.x = h2; h23.y = h3;
        uint2 hv = { *(uint32_t*)&h01, *(uint32_t*)&h23 };
        uint2 lv = { *(uint32_t*)&l01, *(uint32_t*)&l23 };
        ((uint2*)hi)[i] = hv;
        ((uint2*)lo)[i] = lv;
    }
}

// ===========================================================================
// L2-normalize per (row, head), optional logit scale, output fp16 hi/lo split
// ===========================================================================
__global__ __launch_bounds__(256) void normsplit_kernel(
    const float* __restrict__ buf, __half* __restrict__ dh,
    __half* __restrict__ dl, const float* __restrict__ ls, int applyScale)
{
    int gw = (blockIdx.x * 256 + threadIdx.x) >> 5;
    int lane = threadIdx.x & 31;
    if (gw >= M_ * H_) return;
    int m = gw >> 4;
    int h = gw & 15;
    const float* p = buf + (size_t)m * C_ + h * HD_;
    float v0 = p[lane], v1 = p[lane + 32];
    float ss = v0 * v0 + v1 * v1;
    #pragma unroll
    for (int o = 16; o; o >>= 1) ss += __shfl_xor_sync(0xffffffffu, ss, o);
    float inv = rsqrtf(fmaxf(ss, 1e-24f));
    if (applyScale) inv *= __expf(fminf(ls[h], LOGIT_MAX));
    float a0 = v0 * inv, a1 = v1 * inv;
    __half h0 = __float2half_rn(a0), h1 = __float2half_rn(a1);
    size_t o0 = (size_t)m * C_ + h * HD_ + lane;
    dh[o0]      = h0;
    dh[o0 + 32] = h1;
    dl[o0]      = __float2half_rn(a0 - __half2float(h0));
    dl[o0 + 32] = __float2half_rn(a1 - __half2float(h1));
}

// ===========================================================================
// bf16x3 split-precision tensor-core GEMM, 3-stage cp.async, 2 CTAs/SM.
// gridDim.z selects the output slice: z=0 -> F0 fp32, z=1 -> F1 fp32,
// z=2 -> H1/H2 fp16 hi/lo split. A/W/bias indexed by z.
// ===========================================================================
#define GBM 128
#define GBN 128
#define GBK 32
#define SLABB (128*64)
#define BUFB  (4*SLABB)         // 32 KB per stage
#define GSMEM (3*BUFB)          // 96 KB (3-stage), 2 CTAs/SM -> 192 KB

__device__ __forceinline__ void stage8(
    uint32_t nb, const __nv_bfloat16* pah, const __nv_bfloat16* pal,
    const __nv_bfloat16* pwh, const __nv_bfloat16* pwl,
    uint32_t sa0, uint32_t sa1)
{
    cp_async16(nb + sa0,             pah);
    cp_async16(nb + sa1,             pah + 8);
    cp_async16(nb + SLABB + sa0,     pal);
    cp_async16(nb + SLABB + sa1,     pal + 8);
    cp_async16(nb + 2*SLABB + sa0,   pwh);
    cp_async16(nb + 2*SLABB + sa1,   pwh + 8);
    cp_async16(nb + 3*SLABB + sa0,   pwl);
    cp_async16(nb + 3*SLABB + sa1,   pwl + 8);
    CP_COMMIT();
}

__global__ __launch_bounds__(256, 2) void gemm_bf16x3_kernel(
    const __nv_bfloat16* __restrict__ Ah_g, const __nv_bfloat16* __restrict__ Al_g,
    const __nv_bfloat16* __restrict__ Wh_g, const __nv_bfloat16* __restrict__ Wl_g,
    const float* __restrict__ bias, float* __restrict__ F0,
    float* __restrict__ F1, __half* __restrict__ H1, __half* __restrict__ H2,
    int M, int N, int K)
{
    extern __shared__ char smem[];
    const uint32_t sbase = smem_u32(smem);
    const int tid  = threadIdx.x;
    const int warp = tid >> 5, lane = tid & 31;
    const int wm = warp >> 2, wn = warp & 3;
    const int m0 = blockIdx.y * GBM, n0 = blockIdx.x * GBN;
    const int z  = blockIdx.z;

    // z-slice offsets
    Ah_g += (size_t)z * M * K;
    Al_g += (size_t)z * M * K;
    Wh_g += (size_t)z * N * K;
    Wl_g += (size_t)z * N * K;
    bias += z * N;

    // producer strip: row = tid/2, k-half = tid&1
    const int prow = tid >> 1, phalf = tid & 1;
    const size_t aoff = (size_t)(m0 + prow) * K + phalf * 16;
    const size_t boff = (size_t)(n0 + prow) * K + phalf * 16;
    const uint32_t xr = (uint32_t)((prow >> 1) & 3);
    const uint32_t rbyte = (uint32_t)prow * 64;
    const uint32_t c0 = (uint32_t)(phalf * 2);
    const uint32_t sa0 = rbyte + ((c0)     ^ xr) * 16;
    const uint32_t sa1 = rbyte + ((c0 + 1) ^ xr) * 16;

    // fragment address bases
    const int a_lrow = lane & 15;
    const uint32_t a_ksel = (uint32_t)(lane >> 4);
    const uint32_t a_xor = (uint32_t)((a_lrow >> 1) & 3);
    const uint32_t a_rb = (uint32_t)(wm * 64 + a_lrow) * 64;
    const int b_lrow = ((lane >> 4) << 3) + (lane & 7);
    const uint32_t b_ksel = (uint32_t)((lane >> 3) & 1);
    const uint32_t b_xor = (uint32_t)((b_lrow >> 1) & 3);
    const uint32_t b_rb = (uint32_t)(wn * 32 + b_lrow) * 64;

    float acc[4][4][4];
    #pragma unroll
    for (int i = 0; i < 4; i++)
        #pragma unroll
        for (int j = 0; j < 4; j++)
            #pragma unroll
            for (int r = 0; r < 4; r++) acc[i][j][r] = 0.f;

    const int NT = K / GBK;   // 32
    // prologue: stage tiles 0 and 1
    stage8(sbase,        Ah_g + aoff,       Al_g + aoff,
                          Wh_g + boff,       Wl_g + boff,       sa0, sa1);
    stage8(sbase + BUFB, Ah_g + aoff + GBK, Al_g + aoff + GBK,
                          Wh_g + boff + GBK, Wl_g + boff + GBK, sa0, sa1);

    int cs = 0;               // stage of current tile
    int ns = 2;               // stage for tile t+2
    for (int t = 0; t < NT; t++) {
        if (t + 1 < NT) { CP_WAIT1(); } else { CP_WAIT0(); }
        __syncthreads();

        if (t + 2 < NT) {
            const size_t ko = (size_t)(t + 2) * GBK;
            stage8(sbase + ns * BUFB,
                   Ah_g + aoff + ko, Al_g + aoff + ko,
                   Wh_g + boff + ko, Wl_g + boff + ko, sa0, sa1);
        }

        const uint32_t Ahb = sbase + cs * BUFB + a_rb;
        const uint32_t Bhb = sbase + cs * BUFB + 2 * SLABB + b_rb;

        #pragma unroll
        for (int ks = 0; ks < 2; ks++) {
            uint32_t ah[4][4], al[4][4], bh[2][4], bl[2][4];
            const uint32_t ca = (((uint32_t)(ks << 1) + a_ksel) ^ a_xor) * 16;
            const uint32_t cb = (((uint32_t)(ks << 1) + b_ksel) ^ b_xor) * 16;
            #pragma unroll
            for (int mt = 0; mt < 4; mt++) {
                ldsm_x4(ah[mt], Ahb + mt * 1024 + ca);
                ldsm_x4(al[mt], Ahb + SLABB + mt * 1024 + ca);
            }
            #pragma unroll
            for (int np = 0; np < 2; np++) {
                ldsm_x4(bh[np], Bhb + np * 1024 + cb);
                ldsm_x4(bl[np], Bhb + SLABB + np * 1024 + cb);
            }
            #pragma unroll
            for (int mt = 0; mt < 4; mt++)
                #pragma unroll
                for (int nt = 0; nt < 4; nt++) {
                    const uint32_t* bhf = &bh[nt >> 1][(nt & 1) * 2];
                    const uint32_t* blf = &bl[nt >> 1][(nt & 1) * 2];
                    mma_bf16(acc[mt][nt], ah[mt], bhf);
                    mma_bf16(acc[mt][nt], ah[mt], blf);
                    mma_bf16(acc[mt][nt], al[mt], bhf);
                }
        }
        cs = (cs == 2) ? 0 : cs + 1;
        ns = (ns == 2) ? 0 : ns + 1;
    }

    // Epilogue
    const int lr = lane >> 2, lc = lane & 3;
    #pragma unroll
    for (int mt = 0; mt < 4; mt++) {
        const int row = m0 + wm * 64 + mt * 16 + lr;
        #pragma unroll
        for (int nt = 0; nt < 4; nt++) {
            const int col = n0 + wn * 32 + nt * 8 + 2 * lc;
            const float bx = bias[col], by = bias[col + 1];
            float v00 = acc[mt][nt][0] + bx, v01 = acc[mt][nt][1] + by;
            float v10 = acc[mt][nt][2] + bx, v11 = acc[mt][nt][3] + by;
            if (z == 0) {
                float2 o0 = { v00, v01 };
                float2 o1 = { v10, v11 };
                *(float2*)&F0[(size_t)row * N + col]       = o0;
                *(float2*)&F0[(size_t)(row + 8) * N + col] = o1;
            } else if (z == 1) {
                float2 o0 = { v00, v01 };
                float2 o1 = { v10, v11 };
                *(float2*)&F1[(size_t)row * N + col]       = o0;
                *(float2*)&F1[(size_t)(row + 8) * N + col] = o1;
            } else {
                __half h00 = __float2half_rn(v00), h01 = __float2half_rn(v01);
                __half h10 = __float2half_rn(v10), h11 = __float2half_rn(v11);
                __half2 hp0; hp0.x = h00; hp0.y = h01;
                __half2 hp1; hp1.x = h10; hp1.y = h11;
                __half2 lp0 = __floats2half2_rn(v00 - __half2float(h00),
                                                v01 - __half2float(h01));
                __half2 lp1 = __floats2half2_rn(v10 - __half2float(h10),
                                                v11 - __half2float(h11));
                *(__half2*)&H1[(size_t)row * N + col]       = hp0;
                *(__half2*)&H1[(size_t)(row + 8) * N + col] = hp1;
                *(__half2*)&H2[(size_t)row * N + col]       = lp0;
                *(__half2*)&H2[(size_t)(row + 8) * N + col] = lp1;
            }
        }
    }
}

// ===========================================================================
// Tensor-core flash attention (unchanged from R13; emits bf16 split of x).
// ===========================================================================
__global__ __launch_bounds__(256) void attn_mma_kernel(
    const __half* __restrict__ qh, const __half* __restrict__ ql,
    const __half* __restrict__ kh, const __half* __restrict__ kl,
    const __half* __restrict__ vh, const __half* __restrict__ vl,
    __nv_bfloat16* __restrict__ xh, __nv_bfloat16* __restrict__ xl)
{
    __shared__ __align__(1024) uint8_t sm_[32768];
    const uint32_t sb = smem_u32(sm_);
    const uint32_t SKH = 0, SKL = 8192, SVH = 16384, SVL = 24576;
    const int tid = threadIdx.x, w = tid >> 5, lane = tid & 31;
    const int b = blockIdx.y >> 4, h = blockIdx.y & 15;
    const int n0 = blockIdx.x * 128;
    const size_t rs = (size_t)B_ * C_;
    const size_t hb = (size_t)b * C_ + h * 64;

    {
        int row = tid >> 1;
        int cb  = (tid & 1) * 4;
        const uint4* gh = (const uint4*)(qh + (size_t)(n0 + row) * rs + hb);
        const uint4* gl = (const uint4*)(ql + (size_t)(n0 + row) * rs + hb);
        uint32_t rbase = (uint32_t)row * 128;
        #pragma unroll
        for (int c = 0; c < 4; c++) {
            uint32_t sw = ((uint32_t)((cb + c) ^ (row & 7))) * 16;
            *(uint4*)(sm_ + rbase + sw)         = gh[cb + c];
            *(uint4*)(sm_ + 16384 + rbase + sw) = gl[cb + c];
        }
    }
    __syncthreads();

    uint32_t qfh[4][4], qfl[4][4];
    {
        int arow = w * 16 + (lane & 15);
        uint32_t rbase = (uint32_t)arow * 128;
        #pragma unroll
        for (int ks = 0; ks < 4; ks++) {
            uint32_t c = ((uint32_t)((ks * 2 + (lane >> 4)) ^ (arow & 7))) * 16;
            ldsm_x4(qfh[ks], sb + rbase + c);
            ldsm_x4(qfl[ks], sb + 16384 + rbase + c);
        }
    }

    float oacc[8][4];
    #pragma unroll
    for (int i = 0; i < 8; i++)
        #pragma unroll
        for (int j = 0; j < 4; j++) oacc[i][j] = 0.f;
    float m0 = -1e30f, m1 = -1e30f, l0 = 0.f, l1 = 0.f;

    const int b_lrow = ((lane >> 4) << 3) + (lane & 7);
    const uint32_t b_ksel = (uint32_t)((lane >> 3) & 1);
    const int vg = lane >> 3, vidx = lane & 7;

    for (int kt = 0; kt < 16; kt++) {
        __syncthreads();
        {
            int row = tid >> 2;
            int cc0 = (tid & 3) * 2;
            size_t go = (size_t)(kt * 64 + row) * rs + hb;
            const uint4* gkh = (const uint4*)(kh + go);
            const uint4* gkl = (const uint4*)(kl + go);
            const uint4* gvh = (const uint4*)(vh + go);
            const uint4* gvl = (const uint4*)(vl + go);
            uint32_t rbase = (uint32_t)row * 128;
            #pragma unroll
            for (int c = 0; c < 2; c++) {
                uint32_t sw = ((uint32_t)((cc0 + c) ^ (row & 7))) * 16;
                *(uint4*)(sm_ + SKH + rbase + sw) = gkh[cc0 + c];
                *(uint4*)(sm_ + SKL + rbase + sw) = gkl[cc0 + c];
                *(uint4*)(sm_ + SVH + rbase + sw) = gvh[cc0 + c];
                *(uint4*)(sm_ + SVL + rbase + sw) = gvl[cc0 + c];
            }
        }
        __syncthreads();

        float sacc[8][4];
        #pragma unroll
        for (int i = 0; i < 8; i++)
            #pragma unroll
            for (int j = 0; j < 4; j++) sacc[i][j] = 0.f;

        #pragma unroll
        for (int ks = 0; ks < 4; ks++) {
            uint32_t kfh[4][4], kfl[4][4];
            #pragma unroll
            for (int np = 0; np < 4; np++) {
                int row = np * 16 + b_lrow;
                uint32_t a = (uint32_t)row * 128
                           + ((uint32_t)(ks * 2 + b_ksel) ^ (row & 7)) * 16;
                ldsm_x4(kfh[np], sb + SKH + a);
                ldsm_x4(kfl[np], sb + SKL + a);
            }
            #pragma unroll
            for (int np = 0; np < 4; np++)
                #pragma unroll
                for (int sub = 0; sub < 2; sub++) {
                    int nt = np * 2 + sub;
                    mma_f16(sacc[nt], qfh[ks], &kfh[np][sub * 2]);
                    mma_f16(sacc[nt], qfh[ks], &kfl[np][sub * 2]);
                    mma_f16(sacc[nt], qfl[ks], &kfh[np][sub * 2]);
                }
        }

        float tm0 = -1e30f, tm1 = -1e30f;
        #pragma unroll
        for (int nt = 0; nt < 8; nt++) {
            tm0 = fmaxf(tm0, fmaxf(sacc[nt][0], sacc[nt][1]));
            tm1 = fmaxf(tm1, fmaxf(sacc[nt][2], sacc[nt][3]));
        }
        tm0 = fmaxf(tm0, __shfl_xor_sync(0xffffffffu, tm0, 1));
        tm0 = fmaxf(tm0, __shfl_xor_sync(0xffffffffu, tm0, 2));
        tm1 = fmaxf(tm1, __shfl_xor_sync(0xffffffffu, tm1, 1));
        tm1 = fmaxf(tm1, __shfl_xor_sync(0xffffffffu, tm1, 2));
        float mn0 = fmaxf(m0, tm0), mn1 = fmaxf(m1, tm1);
        float cr0 = __expf(m0 - mn0), cr1 = __expf(m1 - mn1);
        l0 *= cr0; l1 *= cr1;
        #pragma unroll
        for (int nt = 0; nt < 8; nt++) {
            oacc[nt][0] *= cr0; oacc[nt][1] *= cr0;
            oacc[nt][2] *= cr1; oacc[nt][3] *= cr1;
        }

        uint32_t pA[4][4];
        float ps0 = 0.f, ps1 = 0.f;
        #pragma unroll
        for (int nt = 0; nt < 8; nt++) {
            float t0 = (sacc[nt][0] - mn0) * L2E_;
            float t1 = (sacc[nt][1] - mn0) * L2E_;
            float t2 = (sacc[nt][2] - mn1) * L2E_;
            float t3 = (sacc[nt][3] - mn1) * L2E_;
            uint32_t pk01, e01, pk23, e23;
            asm("cvt.rn.f16x2.f32 %0, %1, %2;" : "=r"(pk01) : "f"(t1), "f"(t0));
            asm("ex2.approx.f16x2 %0, %1;" : "=r"(e01) : "r"(pk01));
            asm("cvt.rn.f16x2.f32 %0, %1, %2;" : "=r"(pk23) : "f"(t3), "f"(t2));
            asm("ex2.approx.f16x2 %0, %1;" : "=r"(e23) : "r"(pk23));
            float f0, f1, f2, f3;
            asm("{ .reg .b16 a, b; mov.b32 {a, b}, %2;"
                " cvt.f32.f16 %0, a; cvt.f32.f16 %1, b; }"
                : "=f"(f0), "=f"(f1) : "r"(e01));
            asm("{ .reg .b16 a, b; mov.b32 {a, b}, %2;"
                " cvt.f32.f16 %0, a; cvt.f32.f16 %1, b; }"
                : "=f"(f2), "=f"(f3) : "r"(e23));
            ps0 += f0 + f1;
            ps1 += f2 + f3;
            int u = nt >> 1, s2 = (nt & 1) * 2;
            pA[u][s2]     = e01;
            pA[u][s2 + 1] = e23;
        }
        ps0 += __shfl_xor_sync(0xffffffffu, ps0, 1);
        ps0 += __shfl_xor_sync(0xffffffffu, ps0, 2);
        ps1 += __shfl_xor_sync(0xffffffffu, ps1, 1);
        ps1 += __shfl_xor_sync(0xffffffffu, ps1, 2);
        l0 += ps0; l1 += ps1;
        m0 = mn0; m1 = mn1;

        #pragma unroll
        for (int ks = 0; ks < 4; ks++) {
            uint32_t vfh[4][4], vfl[4][4];
            int vrow = ks * 16 + (vg & 1) * 8 + vidx;
            #pragma unroll
            for (int hp = 0; hp < 4; hp++) {
                uint32_t a = (uint32_t)vrow * 128
                           + ((uint32_t)(hp * 2 + (vg >> 1)) ^ (vrow & 7)) * 16;
                ldsm_x4_t(vfh[hp], sb + SVH + a);
                ldsm_x4_t(vfl[hp], sb + SVL + a);
            }
            #pragma unroll
            for (int hp = 0; hp < 4; hp++)
                #pragma unroll
                for (int sub = 0; sub < 2; sub++) {
                    int nt = hp * 2 + sub;
                    mma_f16(oacc[nt], pA[ks], &vfh[hp][sub * 2]);
                    mma_f16(oacc[nt], pA[ks], &vfl[hp][sub * 2]);
                }
        }
    }

    float il0 = 1.f / l0, il1 = 1.f / l1;
    int row0 = n0 + w * 16 + (lane >> 2);
    size_t base0 = (size_t)row0 * rs + hb + (lane & 3) * 2;
    #pragma unroll
    for (int nt = 0; nt < 8; nt++) {
        float a0 = oacc[nt][0] * il0, a1 = oacc[nt][1] * il0;
        float b0 = oacc[nt][2] * il1, b1 = oacc[nt][3] * il1;
        __nv_bfloat16 h0 = __float2bfloat16_rn(a0), h1 = __float2bfloat16_rn(a1);
        __nv_bfloat16 g0 = __float2bfloat16_rn(b0), g1 = __float2bfloat16_rn(b1);
        __nv_bfloat162 hp0; hp0.x = h0; hp0.y = h1;
        __nv_bfloat162 hp1; hp1.x = g0; hp1.y = g1;
        __nv_bfloat162 lp0 = __floats2bfloat162_rn(a0 - __bfloat162float(h0),
                                                   a1 - __bfloat162float(h1));
        __nv_bfloat162 lp1 = __floats2bfloat162_rn(b0 - __bfloat162float(g0),
                                                   b1 - __bfloat162float(g1));
        *(__nv_bfloat162*)&xh[base0 + nt * 8]          = hp0;
        *(__nv_bfloat162*)&xh[base0 + 8 * rs + nt * 8] = hp1;
        *(__nv_bfloat162*)&xl[base0 + nt * 8]          = lp0;
        *(__nv_bfloat162*)&xl[base0 + 8 * rs + nt * 8] = lp1;
    }
}

// ---------------------------------------------------------------------------
// Launcher
// ---------------------------------------------------------------------------
extern "C" void kernel_launch(void* const* d_in, const int* in_sizes, int n_in,
                              void* d_out, int out_size)
{
    const float* query = (const float*)d_in[0];
    const float* key   = (const float*)d_in[1];
    const float* value = (const float*)d_in[2];
    const float* ipw   = (const float*)d_in[3];
    const float* ipb   = (const float*)d_in[4];
    const float* ls    = (const float*)d_in[5];
    const float* outw  = (const float*)d_in[6];
    const float* outb  = (const float*)d_in[7];
    float* out = (float*)d_out;

    float *q, *k;
    __nv_bfloat16 *ah, *al, *wh, *wl;
    __half *qhp, *qlp, *khp, *klp, *vhp, *vlp;
    cudaGetSymbolAddress((void**)&q, g_q);
    cudaGetSymbolAddress((void**)&k, g_k);
    cudaGetSymbolAddress((void**)&ah, g_ah);
    cudaGetSymbolAddress((void**)&al, g_al);
    cudaGetSymbolAddress((void**)&wh, g_wh);
    cudaGetSymbolAddress((void**)&wl, g_wl);
    cudaGetSymbolAddress((void**)&qhp, g_qh);
    cudaGetSymbolAddress((void**)&qlp, g_ql);
    cudaGetSymbolAddress((void**)&khp, g_kh);
    cudaGetSymbolAddress((void**)&klp, g_kl);
    cudaGetSymbolAddress((void**)&vhp, g_vh);
    cudaGetSymbolAddress((void**)&vlp, g_vl);

    static int attr_set = 0;
    if (!attr_set) {
        cudaFuncSetAttribute(gemm_bf16x3_kernel,
                             cudaFuncAttributeMaxDynamicSharedMemorySize, GSMEM);
        attr_set = 1;
    }

    const int n4_mat = (M_ * C_) / 4;
    const int n4_ipw = (3 * C_ * C_) / 4;
    const int n4_ow  = (C_ * C_) / 4;
    const size_t MC = (size_t)M_ * C_;
    const size_t CC = (size_t)C_ * C_;

    // Weight splits
    split_bf16_kernel<<<1184, 256>>>(ipw, wh, wl, n4_ipw);
    split_bf16_kernel<<<592, 256>>>(outw, wh + 3*CC, wl + 3*CC, n4_ow);

    // A-operand splits into 3 slices
    split_bf16_kernel<<<1184, 256>>>(query, ah,          al,          n4_mat);
    split_bf16_kernel<<<1184, 256>>>(key,   ah + MC,     al + MC,     n4_mat);
    split_bf16_kernel<<<1184, 256>>>(value, ah + 2*MC,   al + 2*MC,   n4_mat);

    // Fused QKV projection: z=0 -> q (fp32), z=1 -> k (fp32), z=2 -> v (fp16 split)
    gemm_bf16x3_kernel<<<dim3(C_/GBN, M_/GBM, 3), 256, GSMEM>>>(
        ah, al, wh, wl, ipb, q, k, vhp, vlp, M_, C_, C_);

    // Normalize + fp16-split q (with logit scale) and k
    normsplit_kernel<<<(M_ * H_) / 8, 256>>>(q, qhp, qlp, ls, 1);
    normsplit_kernel<<<(M_ * H_) / 8, 256>>>(k, khp, klp, ls, 0);

    // Tensor-core flash attention -> bf16 split x (reuses ah/al slice 0)
    attn_mma_kernel<<<dim3(N_ / 128, B_ * H_), 256>>>(qhp, qlp, khp, klp,
                                                      vhp, vlp, ah, al);

    // Output projection (z=0 -> fp32 out)
    gemm_bf16x3_kernel<<<dim3(C_/GBN, M_/GBM, 1), 256, GSMEM>>>(
        ah, al, wh + 3*CC, wl + 3*CC, outb,
        out, (float*)0, (__half*)0, (__half*)0, M_, C_, C_);
}